// round 2
// baseline (speedup 1.0000x reference)
#include <cuda_runtime.h>

#define NPOS 1296
#define GRID1D 36
#define PP 7
#define NP 10
#define WINS 20
#define LL 14
#define HH 160
#define WW 160
#define PLANES 32
#define STEPS (NPOS*NP)   // 12960

// ---------------- scratch (static device globals; no runtime allocation) ----
__device__ float          g_M[49*49];              // Wp @ Wb
__device__ float          g_v[NP*49];              // (bp + pos_emb[n]) @ Wb + bb
__device__ float          g_den[(size_t)PLANES*STEPS*49]; // ~81 MB
__device__ unsigned short g_coords[PLANES*STEPS];  // (row0<<8)|col0 per step

// ---------------- K0: fuse the two projections --------------------------------
__global__ void k_precompute(const float* __restrict__ Wp, const float* __restrict__ bp,
                             const float* __restrict__ pe, const float* __restrict__ Wb,
                             const float* __restrict__ bb) {
    int o = blockIdx.x * blockDim.x + threadIdx.x;
    if (o < 49*49) {
        int k = o / 49, q = o % 49;
        float acc = 0.f;
        #pragma unroll 8
        for (int e = 0; e < 128; e++) acc += Wp[k*128 + e] * Wb[e*49 + q];
        g_M[o] = acc;
    } else if (o < 49*49 + NP*49) {
        int oo = o - 49*49;
        int n = oo / 49, q = oo % 49;
        float acc = bb[q];
        #pragma unroll 8
        for (int e = 0; e < 128; e++) acc += (bp[e] + pe[n*128 + e]) * Wb[e*49 + q];
        g_v[oo] = acc;
    }
}

// ---------------- K1: conv + top-10 + den + coords ----------------------------
__global__ __launch_bounds__(256) void k_stage1(const float* __restrict__ images) {
    const int pos   = blockIdx.x;
    const int plane = blockIdx.y;
    const int t     = threadIdx.x;

    const int ixp = pos / GRID1D;      // x outer
    const int iyp = pos % GRID1D;      // y inner
    const int x = ixp * 4, y = iyp * 4;
    const int xb0 = max(x - 7, 0), yb0 = max(y - 7, 0);
    const int winW = min(x + 13, WW) - xb0;
    const int winH = min(y + 13, HH) - yb0;

    __shared__ float sWin[WINS*WINS];
    __shared__ float sRef[49];
    __shared__ float sM[49*49];
    __shared__ float sV[NP*49];
    __shared__ unsigned long long sWarpKey[8];
    __shared__ int   sSel[NP];
    __shared__ float sPatch[NP*49];

    const float* img = images + (size_t)plane * (HH*WW);
    for (int o = t; o < WINS*WINS; o += 256)
        sWin[o] = img[(yb0 + o / WINS) * WW + xb0 + o % WINS];
    if (t < 49) sRef[t] = img[(y + t / 7) * WW + x + t % 7];
    for (int o = t; o < 49*49; o += 256) sM[o] = g_M[o];
    for (int o = t; o < NP*49; o += 256) sV[o] = g_v[o];
    __syncthreads();

    // per-thread sim value (196 outputs)
    float sim = -__int_as_float(0x7f800000); // -inf
    if (t < LL*LL) {
        const int i = t / LL, j = t % LL;
        if (i <= winH - PP && j <= winW - PP) {
            float acc = 0.f;
            #pragma unroll
            for (int dy = 0; dy < PP; dy++)
                #pragma unroll
                for (int dx = 0; dx < PP; dx++)
                    acc += sWin[(i + dy)*WINS + j + dx] * sRef[dy*7 + dx];
            sim = acc;
        }
    }

    const int lane = t & 31, w = t >> 5;
    for (int rnd = 0; rnd < NP; rnd++) {
        unsigned b = __float_as_uint(sim);
        unsigned ord = (b & 0x80000000u) ? ~b : (b | 0x80000000u);
        unsigned long long key = ((unsigned long long)ord << 32) | (unsigned)(1023 - t);
        #pragma unroll
        for (int s = 16; s; s >>= 1) {
            unsigned long long o2 = __shfl_xor_sync(0xffffffffu, key, s);
            if (o2 > key) key = o2;
        }
        if (lane == 0) sWarpKey[w] = key;
        __syncthreads();
        if (t == 0) {
            unsigned long long best = sWarpKey[0];
            #pragma unroll
            for (int ww = 1; ww < 8; ww++) if (sWarpKey[ww] > best) best = sWarpKey[ww];
            sSel[rnd] = 1023 - (int)(best & 1023u);
        }
        __syncthreads();
        if (t == sSel[rnd]) sim = -__int_as_float(0x7f800000);
    }
    __syncthreads();

    // extract transposed patches: patch[n][k] = win[oy + k%7][ox + k/7]
    for (int o = t; o < NP*49; o += 256) {
        int n = o / 49, k = o % 49;
        int id = sSel[n];
        int oy = id / LL, ox = id % LL;
        sPatch[o] = sWin[(oy + k % 7) * WINS + ox + k / 7];
    }
    __syncthreads();

    // den[n][q] = sum_k patch[n][k] * M[k][q] + v[n][q]
    float* denOut = g_den + ((size_t)plane * STEPS + (size_t)pos * NP) * 49;
    for (int o = t; o < NP*49; o += 256) {
        int n = o / 49, q = o % 49;
        const float* pr = sPatch + n*49;
        float acc = sV[o];
        #pragma unroll
        for (int k = 0; k < 49; k++) acc += pr[k] * sM[k*49 + q];
        denOut[o] = acc;
    }
    if (t < NP) {
        int id = sSel[t];
        int oy = id / LL, ox = id % LL;
        int row0 = ox + yb0;  // source bug preserved: row start = col-offset + y-window
        int col0 = oy + xb0;
        g_coords[plane*STEPS + pos*NP + t] = (unsigned short)((row0 << 8) | col0);
    }
}

// ---------------- K2: per-pixel ordered affine fold ---------------------------
__device__ __forceinline__ void frange(int c, int& lo, int& hi) {
    lo = (c <= 19) ? 0 : ((c - 9) >> 2);   // ceil((c-12)/4)
    hi = min(GRID1D - 1, (c + 7) >> 2);
}

__global__ __launch_bounds__(256) void k_fold(const float* __restrict__ images,
                                              float* __restrict__ out) {
    const int plane = blockIdx.y;
    const int pix = blockIdx.x * blockDim.x + threadIdx.x;
    if (pix >= HH*WW) return;
    const int r = pix / WW, cc = pix % WW;

    float val = images[(size_t)plane * (HH*WW) + pix];

    int loCC, hiCC, loR, hiR;
    frange(cc, loCC, hiCC);
    frange(r,  loR,  hiR);
    // im role needs ix in f(cc) and iy in f(r); cnt role needs ix in f(r), iy in f(cc)
    if (loCC > hiCC || loR > hiR) {        // no im touches possible -> output = input
        out[(size_t)plane * (HH*WW) + pix] = val;
        return;
    }

    const unsigned short* coords = g_coords + plane * STEPS;
    const float* den = g_den + (size_t)plane * STEPS * 49;

    float cnt = 1.0f;

    const int xFirst = min(loCC, loR), xLast = max(hiCC, hiR);
    const int xGapEnd = max(loCC, loR);
    const int yFirst = xFirst, yLast = xLast;      // same two intervals, same union
    const int yGapEnd = xGapEnd;

    for (int ix = xFirst; ix <= xLast; ix++) {
        const bool okxIm  = (ix >= loCC) & (ix <= hiCC);
        const bool okxCnt = (ix >= loR)  & (ix <= hiR);
        if (!okxIm && !okxCnt) { ix = xGapEnd - 1; continue; }  // jump over gap
        for (int iy = yFirst; iy <= yLast; iy++) {
            const bool okyIm  = (iy >= loR)  & (iy <= hiR);
            const bool okyCnt = (iy >= loCC) & (iy <= hiCC);
            if (!okyIm && !okyCnt) { iy = yGapEnd - 1; continue; }
            const bool rIm  = okxIm  & okyIm;
            const bool rCnt = okxCnt & okyCnt;
            if (!rIm && !rCnt) continue;

            const int base = (ix * GRID1D + iy) * NP;
            #pragma unroll
            for (int n = 0; n < NP; n++) {
                const unsigned pc = coords[base + n];
                const int row0 = (int)(pc >> 8), col0 = (int)(pc & 255u);
                if (rIm) {
                    const unsigned di = (unsigned)(r - row0), dj = (unsigned)(cc - col0);
                    if (di < 7u && dj < 7u) {
                        const float d = __ldg(den + (size_t)(base + n) * 49 + di*7 + dj);
                        val = (val * cnt + d) / (cnt + 1.0f);
                    }
                }
                if (rCnt) {
                    if ((unsigned)(r - col0) < 7u && (unsigned)(cc - row0) < 7u)
                        cnt += 1.0f;
                }
            }
        }
    }
    out[(size_t)plane * (HH*WW) + pix] = val;
}

// ---------------- launch ------------------------------------------------------
extern "C" void kernel_launch(void* const* d_in, const int* in_sizes, int n_in,
                              void* d_out, int out_size) {
    const float* images = (const float*)d_in[0];
    const float* Wp     = (const float*)d_in[1];
    const float* bp     = (const float*)d_in[2];
    const float* pe     = (const float*)d_in[3];
    const float* Wb     = (const float*)d_in[4];
    const float* bb     = (const float*)d_in[5];
    float* out = (float*)d_out;
    (void)in_sizes; (void)n_in; (void)out_size;

    k_precompute<<<12, 256>>>(Wp, bp, pe, Wb, bb);

    dim3 g1(NPOS, PLANES);
    k_stage1<<<g1, 256>>>(images);

    dim3 g2((HH*WW + 255) / 256, PLANES);
    k_fold<<<g2, 256>>>(images, out);
}

// round 4
// speedup vs baseline: 1.0767x; 1.0767x over previous
#include <cuda_runtime.h>

#define NPOS 1296
#define GRID1D 36
#define PP 7
#define NP 10
#define WINS 20
#define LL 14
#define HH 160
#define WW 160
#define PLANES 32
#define STEPS (NPOS*NP)   // 12960

// ---------------- scratch (static device globals; no runtime allocation) ----
__device__ float          g_M[49*49];              // Wp @ Wb
__device__ float          g_v[NP*49];              // (bp + pos_emb[n]) @ Wb + bb
__device__ float          g_den[(size_t)PLANES*STEPS*49]; // ~81 MB
__device__ unsigned short g_coords[PLANES*STEPS];  // (row0<<8)|col0 per step

// ---------------- K0: fuse the two projections (block per output row) --------
__global__ __launch_bounds__(64) void k_precompute(const float* __restrict__ Wp,
                                                   const float* __restrict__ bp,
                                                   const float* __restrict__ pe,
                                                   const float* __restrict__ Wb,
                                                   const float* __restrict__ bb) {
    const int row = blockIdx.x;   // 0..48 -> M rows, 49..58 -> v rows
    const int t = threadIdx.x;
    __shared__ float sRow[128];
    if (row < 49) {
        for (int e = t; e < 128; e += 64) sRow[e] = Wp[row*128 + e];
    } else {
        const int n = row - 49;
        for (int e = t; e < 128; e += 64) sRow[e] = bp[e] + pe[n*128 + e];
    }
    __syncthreads();
    for (int q = t; q < 49; q += 64) {
        float acc = (row < 49) ? 0.f : bb[q];
        #pragma unroll 8
        for (int e = 0; e < 128; e++) acc += sRow[e] * Wb[e*49 + q];
        if (row < 49) g_M[row*49 + q] = acc;
        else          g_v[(row-49)*49 + q] = acc;
    }
}

// ---------------- K1: conv + rank-based top-10 + den + coords ----------------
__global__ __launch_bounds__(256) void k_stage1(const float* __restrict__ images) {
    const int pos   = blockIdx.x;
    const int plane = blockIdx.y;
    const int t     = threadIdx.x;

    const int ixp = pos / GRID1D;      // x outer
    const int iyp = pos % GRID1D;      // y inner
    const int x = ixp * 4, y = iyp * 4;
    const int xb0 = max(x - 7, 0), yb0 = max(y - 7, 0);
    const int winW = min(x + 13, WW) - xb0;
    const int winH = min(y + 13, HH) - yb0;

    __shared__ float sWin[WINS*WINS];
    __shared__ float sRef[49];
    __shared__ float sM[49*49];
    __shared__ float sV[NP*49];
    __shared__ __align__(16) float sSim[196];
    __shared__ int   sSel[NP];
    __shared__ float sPatch[NP*49];

    const float* img = images + (size_t)plane * (HH*WW);
    for (int o = t; o < WINS*WINS; o += 256)
        sWin[o] = img[(yb0 + o / WINS) * WW + xb0 + o % WINS];
    if (t < 49) sRef[t] = img[(y + t / 7) * WW + x + t % 7];
    for (int o = t; o < 49*49; o += 256) sM[o] = g_M[o];
    for (int o = t; o < NP*49; o += 256) sV[o] = g_v[o];
    __syncthreads();

    // per-thread sim value (196 outputs), invalid -> -inf
    const float NEG_INF = -__int_as_float(0x7f800000);
    if (t < LL*LL) {
        const int i = t / LL, j = t % LL;
        float sim = NEG_INF;
        if (i <= winH - PP && j <= winW - PP) {
            float acc = 0.f;
            #pragma unroll
            for (int dy = 0; dy < PP; dy++)
                #pragma unroll
                for (int dx = 0; dx < PP; dx++)
                    acc += sWin[(i + dy)*WINS + j + dx] * sRef[dy*7 + dx];
            sim = acc;
        }
        sSim[t] = sim;
    }
    __syncthreads();

    // rank-based top-NP selection (stable: ties broken by lower index first)
    if (t < 196) {
        const float v = sSim[t];
        int rank = 0;
        const float4* s4 = (const float4*)sSim;
        #pragma unroll 7
        for (int j4 = 0; j4 < 49; j4++) {
            const float4 vj = s4[j4];
            const int j = j4 * 4;
            rank += (vj.x > v) | ((vj.x == v) & (j + 0 < t));
            rank += (vj.y > v) | ((vj.y == v) & (j + 1 < t));
            rank += (vj.z > v) | ((vj.z == v) & (j + 2 < t));
            rank += (vj.w > v) | ((vj.w == v) & (j + 3 < t));
        }
        if (rank < NP) sSel[rank] = t;
    }
    __syncthreads();

    // extract transposed patches: patch[n][k] = win[oy + k%7][ox + k/7]
    for (int o = t; o < NP*49; o += 256) {
        int n = o / 49, k = o % 49;
        int id = sSel[n];
        int oy = id / LL, ox = id % LL;
        sPatch[o] = sWin[(oy + k % 7) * WINS + ox + k / 7];
    }
    __syncthreads();

    // den[n][q] = sum_k patch[n][k] * M[k][q] + v[n][q]
    float* denOut = g_den + ((size_t)plane * STEPS + (size_t)pos * NP) * 49;
    for (int o = t; o < NP*49; o += 256) {
        int n = o / 49, q = o % 49;
        const float* pr = sPatch + n*49;
        float acc = sV[o];
        #pragma unroll
        for (int k = 0; k < 49; k++) acc += pr[k] * sM[k*49 + q];
        denOut[o] = acc;
    }
    if (t < NP) {
        int id = sSel[t];
        int oy = id / LL, ox = id % LL;
        int row0 = ox + yb0;  // source bug preserved: row start = col-offset + y-window
        int col0 = oy + xb0;
        g_coords[plane*STEPS + pos*NP + t] = (unsigned short)((row0 << 8) | col0);
    }
}

// ---------------- K2: per-pixel two-pass step-ordered fold -------------------
__device__ __forceinline__ int flo(int c) { return (c <= 19) ? 0 : ((c - 9) >> 2); }
__device__ __forceinline__ int fhi(int c) { return min(GRID1D - 1, (c + 7) >> 2); }

#define MAXTOUCH 250

__global__ __launch_bounds__(256) void k_fold(const float* __restrict__ images,
                                              float* __restrict__ out) {
    const int plane = blockIdx.y;
    const int tile  = blockIdx.x;               // 0..99
    const int TR = (tile / 10) * 16, TC = (tile % 10) * 16;
    const int t = threadIdx.x;
    const int r  = TR + (t >> 4);
    const int cc = TC + (t & 15);

    // block-level cell ranges (supersets of every pixel's per-role ranges)
    const int rLo = flo(TR), rHi = fhi(TR + 15);
    const int cLo = flo(TC), cHi = fhi(TC + 15);
    const int rW = rHi - rLo + 1;               // <= 10
    const int cW = cHi - cLo + 1;               // <= 10

    __shared__ unsigned short sImC[10*10*10];   // im rect:  ix in [cLo..cHi], iy in [rLo..rHi]
    __shared__ unsigned short sCntC[10*10*10];  // cnt rect: ix in [rLo..rHi], iy in [cLo..cHi]
    __shared__ float sRecip[256];

    const unsigned short* coords = g_coords + plane * STEPS;

    const int nIm = cW * rW * NP;
    for (int o = t; o < nIm; o += 256) {
        int cell = o / NP, n = o % NP;
        int ixo = cell / rW, iyo = cell % rW;
        sImC[o] = coords[((cLo + ixo) * GRID1D + rLo + iyo) * NP + n];
    }
    const int nCnt = rW * cW * NP;
    for (int o = t; o < nCnt; o += 256) {
        int cell = o / NP, n = o % NP;
        int ixo = cell / cW, iyo = cell % cW;
        sCntC[o] = coords[((rLo + ixo) * GRID1D + cLo + iyo) * NP + n];
    }
    sRecip[t] = (t >= 2) ? (1.0f / (float)t) : 0.f;
    __syncthreads();

    float val = images[(size_t)plane * (HH*WW) + r * WW + cc];

    const int pxCLo = flo(cc), pxCHi = fhi(cc);
    const int pxRLo = flo(r),  pxRHi = fhi(r);
    const bool active = (pxCLo <= pxCHi) && (pxRLo <= pxRHi);

    if (active) {
        // ---- pass 1: record cnt-touch steps (ascending by construction) ----
        unsigned short cntSteps[MAXTOUCH];
        int ncnt = 0;
        for (int ix = pxRLo; ix <= pxRHi; ix++) {
            for (int iy = pxCLo; iy <= pxCHi; iy++) {
                const int so = ((ix - rLo) * cW + (iy - cLo)) * NP;
                const int stepBase = (ix * GRID1D + iy) * NP;
                #pragma unroll
                for (int n = 0; n < NP; n++) {
                    const unsigned pc = sCntC[so + n];
                    const int row0 = (int)(pc >> 8), col0 = (int)(pc & 255u);
                    if ((unsigned)(r - col0) < 7u && (unsigned)(cc - row0) < 7u)
                        cntSteps[ncnt++] = (unsigned short)(stepBase + n);
                }
            }
        }
        // ---- pass 2: im touches (ascending), merge pointer gives count ----
        const float* den = g_den + (size_t)plane * STEPS * 49;
        int p = 0;
        for (int ix = pxCLo; ix <= pxCHi; ix++) {
            for (int iy = pxRLo; iy <= pxRHi; iy++) {
                const int so = ((ix - cLo) * rW + (iy - rLo)) * NP;
                const int stepBase = (ix * GRID1D + iy) * NP;
                #pragma unroll
                for (int n = 0; n < NP; n++) {
                    const unsigned pc = sImC[so + n];
                    const int row0 = (int)(pc >> 8), col0 = (int)(pc & 255u);
                    const unsigned di = (unsigned)(r - row0), dj = (unsigned)(cc - col0);
                    if (di < 7u && dj < 7u) {
                        const int step = stepBase + n;
                        while (p < ncnt && (int)cntSteps[p] < step) p++;
                        const float cntv = (float)(1 + p);
                        const float d = __ldg(den + (size_t)step * 49 + di * 7 + dj);
                        val = (val * cntv + d) * sRecip[p + 2];
                    }
                }
            }
        }
    }
    out[(size_t)plane * (HH*WW) + r * WW + cc] = val;
}

// ---------------- launch ------------------------------------------------------
extern "C" void kernel_launch(void* const* d_in, const int* in_sizes, int n_in,
                              void* d_out, int out_size) {
    const float* images = (const float*)d_in[0];
    const float* Wp     = (const float*)d_in[1];
    const float* bp     = (const float*)d_in[2];
    const float* pe     = (const float*)d_in[3];
    const float* Wb     = (const float*)d_in[4];
    const float* bb     = (const float*)d_in[5];
    float* out = (float*)d_out;
    (void)in_sizes; (void)n_in; (void)out_size;

    k_precompute<<<59, 64>>>(Wp, bp, pe, Wb, bb);

    dim3 g1(NPOS, PLANES);
    k_stage1<<<g1, 256>>>(images);

    dim3 g2(100, PLANES);
    k_fold<<<g2, 256>>>(images, out);
}

// round 5
// speedup vs baseline: 1.1459x; 1.0644x over previous
#include <cuda_runtime.h>

#define NPOS 1296
#define GRID1D 36
#define PP 7
#define NP 10
#define WINS 20
#define LL 14
#define HH 160
#define WW 160
#define PLANES 32
#define STEPS (NPOS*NP)   // 12960

// ---------------- scratch (static device globals; no runtime allocation) ----
__device__ float          g_M[49*49];              // Wp @ Wb
__device__ float          g_v[NP*49];              // (bp + pos_emb[n]) @ Wb + bb
__device__ float          g_den[(size_t)PLANES*STEPS*49]; // ~81 MB
__device__ unsigned short g_coords[PLANES*STEPS];  // (row0<<8)|col0 per step

// ---------------- K0: fuse the two projections (block per output row) --------
__global__ __launch_bounds__(64) void k_precompute(const float* __restrict__ Wp,
                                                   const float* __restrict__ bp,
                                                   const float* __restrict__ pe,
                                                   const float* __restrict__ Wb,
                                                   const float* __restrict__ bb) {
    const int row = blockIdx.x;   // 0..48 -> M rows, 49..58 -> v rows
    const int t = threadIdx.x;
    __shared__ float sRow[128];
    if (row < 49) {
        for (int e = t; e < 128; e += 64) sRow[e] = Wp[row*128 + e];
    } else {
        const int n = row - 49;
        for (int e = t; e < 128; e += 64) sRow[e] = bp[e] + pe[n*128 + e];
    }
    __syncthreads();
    for (int q = t; q < 49; q += 64) {
        float acc = (row < 49) ? 0.f : bb[q];
        #pragma unroll 8
        for (int e = 0; e < 128; e++) acc += sRow[e] * Wb[e*49 + q];
        if (row < 49) g_M[row*49 + q] = acc;
        else          g_v[(row-49)*49 + q] = acc;
    }
}

// ---------------- K1: conv + rank-based top-10 + den + coords ----------------
__global__ __launch_bounds__(256) void k_stage1(const float* __restrict__ images) {
    const int pos   = blockIdx.x;
    const int plane = blockIdx.y;
    const int t     = threadIdx.x;

    const int ixp = pos / GRID1D;      // x outer
    const int iyp = pos % GRID1D;      // y inner
    const int x = ixp * 4, y = iyp * 4;
    const int xb0 = max(x - 7, 0), yb0 = max(y - 7, 0);
    const int winW = min(x + 13, WW) - xb0;
    const int winH = min(y + 13, HH) - yb0;

    __shared__ float sWin[WINS*WINS];
    __shared__ float sRef[49];
    __shared__ float sM[49*49];
    __shared__ float sV[NP*49];
    __shared__ __align__(16) float sSim[196];
    __shared__ int   sSel[NP];
    __shared__ __align__(16) float sPT[49*12];   // transposed, padded patches

    const float* img = images + (size_t)plane * (HH*WW);
    for (int o = t; o < WINS*WINS; o += 256)
        sWin[o] = img[(yb0 + o / WINS) * WW + xb0 + o % WINS];
    if (t < 49) sRef[t] = img[(y + t / 7) * WW + x + t % 7];
    for (int o = t; o < 49*49; o += 256) sM[o] = g_M[o];
    for (int o = t; o < NP*49; o += 256) sV[o] = g_v[o];
    __syncthreads();

    // per-thread sim value (196 outputs), invalid -> -inf
    const float NEG_INF = -__int_as_float(0x7f800000);
    if (t < LL*LL) {
        const int i = t / LL, j = t % LL;
        float sim = NEG_INF;
        if (i <= winH - PP && j <= winW - PP) {
            float acc = 0.f;
            #pragma unroll
            for (int dy = 0; dy < PP; dy++)
                #pragma unroll
                for (int dx = 0; dx < PP; dx++)
                    acc += sWin[(i + dy)*WINS + j + dx] * sRef[dy*7 + dx];
            sim = acc;
        }
        sSim[t] = sim;
    }
    __syncthreads();

    // rank-based top-NP selection (stable: ties broken by lower index first)
    if (t < 196) {
        const float v = sSim[t];
        int rank = 0;
        const float4* s4 = (const float4*)sSim;
        #pragma unroll 7
        for (int j4 = 0; j4 < 49; j4++) {
            const float4 vj = s4[j4];
            const int j = j4 * 4;
            rank += (vj.x > v) | ((vj.x == v) & (j + 0 < t));
            rank += (vj.y > v) | ((vj.y == v) & (j + 1 < t));
            rank += (vj.z > v) | ((vj.z == v) & (j + 2 < t));
            rank += (vj.w > v) | ((vj.w == v) & (j + 3 < t));
        }
        if (rank < NP) sSel[rank] = t;
    }
    __syncthreads();

    // extract transposed patches into padded-transposed layout:
    // sPT[k*12 + n] = win[oy_n + k%7][ox_n + k/7]
    for (int o = t; o < 49*NP; o += 256) {
        int k = o / NP, n = o - k*NP;
        int id = sSel[n];
        int oy = id / LL, ox = id % LL;
        sPT[k*12 + n] = sWin[(oy + k % 7) * WINS + ox + k / 7];
    }
    __syncthreads();

    // den[n][q] = sum_k patchT[k][n] * M[k][q] + v[n][q]
    // one thread per q; acc[10] in registers; 4 smem wavefronts per k per warp
    if (t < 49) {
        float a0=0.f,a1=0.f,a2=0.f,a3=0.f,a4=0.f,a5=0.f,a6=0.f,a7=0.f,a8=0.f,a9=0.f;
        const float4* P4 = (const float4*)sPT;
        #pragma unroll 7
        for (int k = 0; k < 49; k++) {
            const float m = sM[k*49 + t];
            const float4 pa = P4[k*3 + 0];
            const float4 pb = P4[k*3 + 1];
            const float4 pc = P4[k*3 + 2];
            a0 += m * pa.x; a1 += m * pa.y; a2 += m * pa.z; a3 += m * pa.w;
            a4 += m * pb.x; a5 += m * pb.y; a6 += m * pb.z; a7 += m * pb.w;
            a8 += m * pc.x; a9 += m * pc.y;
        }
        float* denOut = g_den + ((size_t)plane * STEPS + (size_t)pos * NP) * 49;
        denOut[0*49 + t] = a0 + sV[0*49 + t];
        denOut[1*49 + t] = a1 + sV[1*49 + t];
        denOut[2*49 + t] = a2 + sV[2*49 + t];
        denOut[3*49 + t] = a3 + sV[3*49 + t];
        denOut[4*49 + t] = a4 + sV[4*49 + t];
        denOut[5*49 + t] = a5 + sV[5*49 + t];
        denOut[6*49 + t] = a6 + sV[6*49 + t];
        denOut[7*49 + t] = a7 + sV[7*49 + t];
        denOut[8*49 + t] = a8 + sV[8*49 + t];
        denOut[9*49 + t] = a9 + sV[9*49 + t];
    }
    if (t >= 64 && t < 64 + NP) {
        int n = t - 64;
        int id = sSel[n];
        int oy = id / LL, ox = id % LL;
        int row0 = ox + yb0;  // source bug preserved: row start = col-offset + y-window
        int col0 = oy + xb0;
        g_coords[plane*STEPS + pos*NP + n] = (unsigned short)((row0 << 8) | col0);
    }
}

// ---------------- K2: per-pixel two-pass step-ordered fold -------------------
__device__ __forceinline__ int flo(int c) { return (c <= 19) ? 0 : ((c - 9) >> 2); }
__device__ __forceinline__ int fhi(int c) { return min(GRID1D - 1, (c + 7) >> 2); }

#define MAXTOUCH 250

__global__ __launch_bounds__(256) void k_fold(const float* __restrict__ images,
                                              float* __restrict__ out) {
    const int plane = blockIdx.y;
    const int tile  = blockIdx.x;               // 0..99
    const int TR = (tile / 10) * 16, TC = (tile % 10) * 16;
    const int t = threadIdx.x;
    const int r  = TR + (t >> 4);
    const int cc = TC + (t & 15);

    // block-level cell ranges (supersets of every pixel's per-role ranges)
    const int rLo = flo(TR), rHi = fhi(TR + 15);
    const int cLo = flo(TC), cHi = fhi(TC + 15);
    const int rW = rHi - rLo + 1;               // <= 10
    const int cW = cHi - cLo + 1;               // <= 10

    __shared__ __align__(4) unsigned short sImC[10*10*10];   // im rect:  ix in [cLo..cHi], iy in [rLo..rHi]
    __shared__ __align__(4) unsigned short sCntC[10*10*10];  // cnt rect: ix in [rLo..rHi], iy in [cLo..cHi]
    __shared__ float sRecip[256];

    const unsigned short* coords = g_coords + plane * STEPS;

    const int nIm = cW * rW * NP;
    for (int o = t; o < nIm; o += 256) {
        int cell = o / NP, n = o % NP;
        int ixo = cell / rW, iyo = cell % rW;
        sImC[o] = coords[((cLo + ixo) * GRID1D + rLo + iyo) * NP + n];
    }
    const int nCnt = rW * cW * NP;
    for (int o = t; o < nCnt; o += 256) {
        int cell = o / NP, n = o % NP;
        int ixo = cell / cW, iyo = cell % cW;
        sCntC[o] = coords[((rLo + ixo) * GRID1D + cLo + iyo) * NP + n];
    }
    sRecip[t] = (t >= 2) ? (1.0f / (float)t) : 0.f;
    __syncthreads();

    float val = images[(size_t)plane * (HH*WW) + r * WW + cc];

    const int pxCLo = flo(cc), pxCHi = fhi(cc);
    const int pxRLo = flo(r),  pxRHi = fhi(r);
    const bool active = (pxCLo <= pxCHi) && (pxRLo <= pxRHi);

    if (active) {
        const unsigned* sCnt32 = (const unsigned*)sCntC;
        const unsigned* sIm32  = (const unsigned*)sImC;

        // ---- pass 1: record cnt-touch steps (ascending by construction) ----
        unsigned short cntSteps[MAXTOUCH];
        int ncnt = 0;
        for (int ix = pxRLo; ix <= pxRHi; ix++) {
            for (int iy = pxCLo; iy <= pxCHi; iy++) {
                const int cell = (ix - rLo) * cW + (iy - cLo);
                const int so2 = cell * 5;                    // u32 index (NP/2 per cell)
                const int stepBase = (ix * GRID1D + iy) * NP;
                #pragma unroll
                for (int n2 = 0; n2 < 5; n2++) {
                    const unsigned two = sCnt32[so2 + n2];
                    const int col0a = (int)(two & 255u), row0a = (int)((two >> 8) & 255u);
                    if ((unsigned)(r - col0a) < 7u && (unsigned)(cc - row0a) < 7u)
                        cntSteps[ncnt++] = (unsigned short)(stepBase + 2*n2);
                    const int col0b = (int)((two >> 16) & 255u), row0b = (int)(two >> 24);
                    if ((unsigned)(r - col0b) < 7u && (unsigned)(cc - row0b) < 7u)
                        cntSteps[ncnt++] = (unsigned short)(stepBase + 2*n2 + 1);
                }
            }
        }
        // ---- pass 2: im touches (ascending), merge pointer gives count ----
        const float* den = g_den + (size_t)plane * STEPS * 49;
        int p = 0;
        for (int ix = pxCLo; ix <= pxCHi; ix++) {
            for (int iy = pxRLo; iy <= pxRHi; iy++) {
                const int cell = (ix - cLo) * rW + (iy - rLo);
                const int so2 = cell * 5;
                const int stepBase = (ix * GRID1D + iy) * NP;
                #pragma unroll
                for (int n2 = 0; n2 < 5; n2++) {
                    const unsigned two = sIm32[so2 + n2];
                    const int row0a = (int)((two >> 8) & 255u), col0a = (int)(two & 255u);
                    const unsigned dia = (unsigned)(r - row0a), dja = (unsigned)(cc - col0a);
                    if (dia < 7u && dja < 7u) {
                        const int step = stepBase + 2*n2;
                        while (p < ncnt && (int)cntSteps[p] < step) p++;
                        const float cntv = (float)(1 + p);
                        const float d = __ldg(den + (size_t)step * 49 + dia * 7 + dja);
                        val = (val * cntv + d) * sRecip[p + 2];
                    }
                    const int row0b = (int)(two >> 24), col0b = (int)((two >> 16) & 255u);
                    const unsigned dib = (unsigned)(r - row0b), djb = (unsigned)(cc - col0b);
                    if (dib < 7u && djb < 7u) {
                        const int step = stepBase + 2*n2 + 1;
                        while (p < ncnt && (int)cntSteps[p] < step) p++;
                        const float cntv = (float)(1 + p);
                        const float d = __ldg(den + (size_t)step * 49 + dib * 7 + djb);
                        val = (val * cntv + d) * sRecip[p + 2];
                    }
                }
            }
        }
    }
    out[(size_t)plane * (HH*WW) + r * WW + cc] = val;
}

// ---------------- launch ------------------------------------------------------
extern "C" void kernel_launch(void* const* d_in, const int* in_sizes, int n_in,
                              void* d_out, int out_size) {
    const float* images = (const float*)d_in[0];
    const float* Wp     = (const float*)d_in[1];
    const float* bp     = (const float*)d_in[2];
    const float* pe     = (const float*)d_in[3];
    const float* Wb     = (const float*)d_in[4];
    const float* bb     = (const float*)d_in[5];
    float* out = (float*)d_out;
    (void)in_sizes; (void)n_in; (void)out_size;

    k_precompute<<<59, 64>>>(Wp, bp, pe, Wb, bb);

    dim3 g1(NPOS, PLANES);
    k_stage1<<<g1, 256>>>(images);

    dim3 g2(100, PLANES);
    k_fold<<<g2, 256>>>(images, out);
}

// round 6
// speedup vs baseline: 1.1794x; 1.0292x over previous
#include <cuda_runtime.h>

#define NPOS 1296
#define GRID1D 36
#define PP 7
#define NP 10
#define WINS 20
#define LL 14
#define HH 160
#define WW 160
#define PLANES 32
#define STEPS (NPOS*NP)   // 12960

// ---------------- scratch (static device globals; no runtime allocation) ----
__device__ float    g_M[49*49];              // Wp @ Wb
__device__ float    g_v[NP*49];              // (bp + pos_emb[n]) @ Wb + bb
__device__ float    g_den[(size_t)PLANES*STEPS*49]; // ~81 MB
__device__ unsigned g_rowsU[(size_t)PLANES*NPOS*3]; // row0 bytes, 4/u32, pad=200
__device__ unsigned g_colsU[(size_t)PLANES*NPOS*3]; // col0 bytes

// ---------------- K0: fuse the two projections (block per output row) --------
__global__ __launch_bounds__(64) void k_precompute(const float* __restrict__ Wp,
                                                   const float* __restrict__ bp,
                                                   const float* __restrict__ pe,
                                                   const float* __restrict__ Wb,
                                                   const float* __restrict__ bb) {
    const int row = blockIdx.x;   // 0..48 -> M rows, 49..58 -> v rows
    const int t = threadIdx.x;
    __shared__ float sRow[128];
    if (row < 49) {
        for (int e = t; e < 128; e += 64) sRow[e] = Wp[row*128 + e];
    } else {
        const int n = row - 49;
        for (int e = t; e < 128; e += 64) sRow[e] = bp[e] + pe[n*128 + e];
    }
    __syncthreads();
    for (int q = t; q < 49; q += 64) {
        float acc = (row < 49) ? 0.f : bb[q];
        #pragma unroll 8
        for (int e = 0; e < 128; e++) acc += sRow[e] * Wb[e*49 + q];
        if (row < 49) g_M[row*49 + q] = acc;
        else          g_v[(row-49)*49 + q] = acc;
    }
}

// ---------------- K1: conv + rank-based top-10 + den + coord bytes ----------
__global__ __launch_bounds__(256) void k_stage1(const float* __restrict__ images) {
    const int pos   = blockIdx.x;
    const int plane = blockIdx.y;
    const int t     = threadIdx.x;

    const int ixp = pos / GRID1D;      // x outer
    const int iyp = pos % GRID1D;      // y inner
    const int x = ixp * 4, y = iyp * 4;
    const int xb0 = max(x - 7, 0), yb0 = max(y - 7, 0);
    const int winW = min(x + 13, WW) - xb0;
    const int winH = min(y + 13, HH) - yb0;

    __shared__ float sWin[WINS*WINS];
    __shared__ float sRef[49];
    __shared__ float sM[49*49];
    __shared__ float sV[NP*49];
    __shared__ __align__(16) float sSim[196];
    __shared__ int   sSel[NP];
    __shared__ __align__(16) float sPT[49*12];   // transposed, padded patches
    __shared__ unsigned char sRow8[12], sCol8[12];

    const float* img = images + (size_t)plane * (HH*WW);
    for (int o = t; o < WINS*WINS; o += 256)
        sWin[o] = img[(yb0 + o / WINS) * WW + xb0 + o % WINS];
    if (t < 49) sRef[t] = img[(y + t / 7) * WW + x + t % 7];
    for (int o = t; o < 49*49; o += 256) sM[o] = g_M[o];
    for (int o = t; o < NP*49; o += 256) sV[o] = g_v[o];
    __syncthreads();

    // per-thread sim value (196 outputs), invalid -> -inf
    const float NEG_INF = -__int_as_float(0x7f800000);
    if (t < LL*LL) {
        const int i = t / LL, j = t % LL;
        float sim = NEG_INF;
        if (i <= winH - PP && j <= winW - PP) {
            float acc = 0.f;
            #pragma unroll
            for (int dy = 0; dy < PP; dy++)
                #pragma unroll
                for (int dx = 0; dx < PP; dx++)
                    acc += sWin[(i + dy)*WINS + j + dx] * sRef[dy*7 + dx];
            sim = acc;
        }
        sSim[t] = sim;
    }
    __syncthreads();

    // rank-based top-NP selection (stable: ties broken by lower index first)
    if (t < 196) {
        const float v = sSim[t];
        int rank = 0;
        const float4* s4 = (const float4*)sSim;
        #pragma unroll 7
        for (int j4 = 0; j4 < 49; j4++) {
            const float4 vj = s4[j4];
            const int j = j4 * 4;
            rank += (vj.x > v) | ((vj.x == v) & (j + 0 < t));
            rank += (vj.y > v) | ((vj.y == v) & (j + 1 < t));
            rank += (vj.z > v) | ((vj.z == v) & (j + 2 < t));
            rank += (vj.w > v) | ((vj.w == v) & (j + 3 < t));
        }
        if (rank < NP) sSel[rank] = t;
    }
    __syncthreads();

    // extract transposed patches into padded-transposed layout:
    // sPT[k*12 + n] = win[oy_n + k%7][ox_n + k/7]
    for (int o = t; o < 49*NP; o += 256) {
        int k = o / NP, n = o - k*NP;
        int id = sSel[n];
        int oy = id / LL, ox = id % LL;
        sPT[k*12 + n] = sWin[(oy + k % 7) * WINS + ox + k / 7];
    }
    // coord bytes (source bug preserved: row0 = col-offset + yb0, col0 = row-offset + xb0)
    if (t >= 64 && t < 64 + 12) {
        int n = t - 64;
        if (n < NP) {
            int id = sSel[n];
            int oy = id / LL, ox = id % LL;
            sRow8[n] = (unsigned char)(ox + yb0);
            sCol8[n] = (unsigned char)(oy + xb0);
        } else {
            sRow8[n] = 200; sCol8[n] = 200;   // pad: never matches
        }
    }
    __syncthreads();

    // den[n][q] = sum_k patchT[k][n] * M[k][q] + v[n][q]
    if (t < 49) {
        float a0=0.f,a1=0.f,a2=0.f,a3=0.f,a4=0.f,a5=0.f,a6=0.f,a7=0.f,a8=0.f,a9=0.f;
        const float4* P4 = (const float4*)sPT;
        #pragma unroll 7
        for (int k = 0; k < 49; k++) {
            const float m = sM[k*49 + t];
            const float4 pa = P4[k*3 + 0];
            const float4 pb = P4[k*3 + 1];
            const float4 pc = P4[k*3 + 2];
            a0 += m * pa.x; a1 += m * pa.y; a2 += m * pa.z; a3 += m * pa.w;
            a4 += m * pb.x; a5 += m * pb.y; a6 += m * pb.z; a7 += m * pb.w;
            a8 += m * pc.x; a9 += m * pc.y;
        }
        float* denOut = g_den + ((size_t)plane * STEPS + (size_t)pos * NP) * 49;
        denOut[0*49 + t] = a0 + sV[0*49 + t];
        denOut[1*49 + t] = a1 + sV[1*49 + t];
        denOut[2*49 + t] = a2 + sV[2*49 + t];
        denOut[3*49 + t] = a3 + sV[3*49 + t];
        denOut[4*49 + t] = a4 + sV[4*49 + t];
        denOut[5*49 + t] = a5 + sV[5*49 + t];
        denOut[6*49 + t] = a6 + sV[6*49 + t];
        denOut[7*49 + t] = a7 + sV[7*49 + t];
        denOut[8*49 + t] = a8 + sV[8*49 + t];
        denOut[9*49 + t] = a9 + sV[9*49 + t];
    }
    if (t >= 64 && t < 70) {
        int w = t - 64;               // 0..5
        int widx = w % 3;
        const unsigned char* src = (w < 3) ? sRow8 : sCol8;
        unsigned v = (unsigned)src[widx*4 + 0]
                   | ((unsigned)src[widx*4 + 1] << 8)
                   | ((unsigned)src[widx*4 + 2] << 16)
                   | ((unsigned)src[widx*4 + 3] << 24);
        unsigned* dst = (w < 3) ? g_rowsU : g_colsU;
        dst[((size_t)plane*NPOS + pos)*3 + widx] = v;
    }
}

// ---------------- K2: single-pass union-order fold with byte-SIMD checks ----
__device__ __forceinline__ int flo(int c) { return (c <= 19) ? 0 : ((c - 9) >> 2); }
__device__ __forceinline__ int fhi(int c) { return min(GRID1D - 1, (c + 7) >> 2); }
__device__ __forceinline__ unsigned pack4(unsigned hm) {
    return ((hm & 0x01010101u) * 0x01020408u) >> 24;   // byte flags -> 4 bits
}

__global__ __launch_bounds__(256) void k_fold(const float* __restrict__ images,
                                              float* __restrict__ out) {
    const int plane = blockIdx.y;
    const int tile  = blockIdx.x;               // 0..99
    const int TR = (tile / 10) * 16, TC = (tile % 10) * 16;
    const int t = threadIdx.x;
    const int r  = TR + (t >> 4);
    const int cc = TC + (t & 15);

    // block-level axis intervals (same for x and y axes)
    const int Rlo = flo(TR), Rhi = fhi(TR + 15);
    const int Clo = flo(TC), Chi = fhi(TC + 15);
    int l1, h1, l2, h2;
    if (Rlo <= Clo) { l1 = Rlo; h1 = Rhi; l2 = Clo; h2 = Chi; }
    else            { l1 = Clo; h1 = Chi; l2 = Rlo; h2 = Rhi; }
    if (l2 <= h1 + 1) { h1 = max(h1, h2); l2 = 1000; h2 = 999; }   // merged
    const int aLo = l1, aHi = h1, aW = h1 - l1 + 1;
    const int bLo = l2;
    const int bW  = (l2 < 1000) ? (h2 - l2 + 1) : 0;
    const int tot = aW + bW;                    // <= 20

    __shared__ unsigned sRowsU[400*3];
    __shared__ unsigned sColsU[400*3];
    __shared__ float sRecip[256];

    // stage used quadrants of the tot x tot cell grid
    for (int s = t; s < tot*tot; s += 256) {
        const int sx = s / tot, sy = s - sx*tot;
        const int ix = (sx < aW) ? aLo + sx : bLo + sx - aW;
        const int iy = (sy < aW) ? aLo + sy : bLo + sy - aW;
        const bool xC = (ix >= Clo) & (ix <= Chi), xR = (ix >= Rlo) & (ix <= Rhi);
        const bool yC = (iy >= Clo) & (iy <= Chi), yR = (iy >= Rlo) & (iy <= Rhi);
        if ((xC & yR) | (xR & yC)) {
            const size_t g = ((size_t)plane*NPOS + ix*GRID1D + iy)*3;
            const int o = s*3;
            sRowsU[o+0] = g_rowsU[g+0]; sRowsU[o+1] = g_rowsU[g+1]; sRowsU[o+2] = g_rowsU[g+2];
            sColsU[o+0] = g_colsU[g+0]; sColsU[o+1] = g_colsU[g+1]; sColsU[o+2] = g_colsU[g+2];
        }
    }
    sRecip[t] = (t >= 1) ? (1.0f / (float)t) : 0.f;
    __syncthreads();

    float val = images[(size_t)plane * (HH*WW) + r * WW + cc];

    // im role: ix in f(cc), iy in f(r).  cnt role: ix in f(r), iy in f(cc).
    const int imXLo = flo(cc), imXHi = fhi(cc);
    const int cnXLo = flo(r),  cnXHi = fhi(r);
    const bool active = (imXLo <= imXHi) && (cnXLo <= cnXHi);

    if (active) {
        const float* den = g_den + (size_t)plane * STEPS * 49;
        const unsigned rrep = (unsigned)r * 0x01010101u;
        const unsigned crep = (unsigned)cc * 0x01010101u;
        const unsigned seven = 0x07070707u;
        int pcnt = 1;

        const int xF = min(imXLo, cnXLo), xL = max(imXHi, cnXHi);
        const int xGap = max(imXLo, cnXLo);

        for (int ix = xF; ix <= xL; ix++) {
            const bool okIm = (ix >= imXLo) & (ix <= imXHi);
            const bool okCn = (ix >= cnXLo) & (ix <= cnXHi);
            if (!okIm && !okCn) { ix = xGap - 1; continue; }
            const int sx = (ix <= aHi) ? ix - aLo : aW + ix - bLo;
            const int sxBase = sx * tot;

            int yF, yL, yGap;
            if (okIm && okCn) { yF = xF; yL = xL; yGap = xGap; }
            else if (okIm)    { yF = cnXLo; yL = cnXHi; yGap = yF; }   // iy in f(r)
            else              { yF = imXLo; yL = imXHi; yGap = yF; }   // iy in f(cc)

            for (int iy = yF; iy <= yL; iy++) {
                const bool hIm = okIm & (iy >= cnXLo) & (iy <= cnXHi);
                const bool hCn = okCn & (iy >= imXLo) & (iy <= imXHi);
                if (!hIm && !hCn) { iy = yGap - 1; continue; }
                const int sy = (iy <= aHi) ? iy - aLo : aW + iy - bLo;
                const int o = (sxBase + sy) * 3;
                const unsigned R0 = sRowsU[o], R1 = sRowsU[o+1], R2 = sRowsU[o+2];
                const unsigned C0 = sColsU[o], C1 = sColsU[o+1], C2 = sColsU[o+2];
                const int stepBase = (ix*GRID1D + iy) * NP;

                unsigned maskIm = 0, maskCn = 0;
                unsigned rw0=0, rw1=0, rw2=0, cw0=0, cw1=0, cw2=0;
                if (hIm) {
                    rw0 = __vsub4(rrep, R0); rw1 = __vsub4(rrep, R1); rw2 = __vsub4(rrep, R2);
                    cw0 = __vsub4(crep, C0); cw1 = __vsub4(crep, C1); cw2 = __vsub4(crep, C2);
                    maskIm = pack4(__vcmpltu4(rw0, seven) & __vcmpltu4(cw0, seven))
                           | (pack4(__vcmpltu4(rw1, seven) & __vcmpltu4(cw1, seven)) << 4)
                           | (pack4(__vcmpltu4(rw2, seven) & __vcmpltu4(cw2, seven)) << 8);
                }
                if (hCn) {
                    const unsigned a0 = __vsub4(rrep, C0), a1 = __vsub4(rrep, C1), a2 = __vsub4(rrep, C2);
                    const unsigned b0 = __vsub4(crep, R0), b1 = __vsub4(crep, R1), b2 = __vsub4(crep, R2);
                    maskCn = pack4(__vcmpltu4(a0, seven) & __vcmpltu4(b0, seven))
                           | (pack4(__vcmpltu4(a1, seven) & __vcmpltu4(b1, seven)) << 4)
                           | (pack4(__vcmpltu4(a2, seven) & __vcmpltu4(b2, seven)) << 8);
                }
                unsigned m = maskIm | maskCn;
                while (m) {
                    const int n = __ffs(m) - 1; m &= m - 1;
                    if ((maskIm >> n) & 1) {
                        const unsigned rw = (n < 4) ? rw0 : ((n < 8) ? rw1 : rw2);
                        const unsigned cw = (n < 4) ? cw0 : ((n < 8) ? cw1 : cw2);
                        const int sh = (n & 3) * 8;
                        const int di = (rw >> sh) & 0xff, dj = (cw >> sh) & 0xff;
                        const float d = __ldg(den + (size_t)(stepBase + n) * 49 + di*7 + dj);
                        val = (val * (float)pcnt + d) * sRecip[pcnt + 1];
                    }
                    pcnt += (maskCn >> n) & 1;
                }
            }
        }
    }
    out[(size_t)plane * (HH*WW) + r * WW + cc] = val;
}

// ---------------- launch ------------------------------------------------------
extern "C" void kernel_launch(void* const* d_in, const int* in_sizes, int n_in,
                              void* d_out, int out_size) {
    const float* images = (const float*)d_in[0];
    const float* Wp     = (const float*)d_in[1];
    const float* bp     = (const float*)d_in[2];
    const float* pe     = (const float*)d_in[3];
    const float* Wb     = (const float*)d_in[4];
    const float* bb     = (const float*)d_in[5];
    float* out = (float*)d_out;
    (void)in_sizes; (void)n_in; (void)out_size;

    k_precompute<<<59, 64>>>(Wp, bp, pe, Wb, bb);

    dim3 g1(NPOS, PLANES);
    k_stage1<<<g1, 256>>>(images);

    dim3 g2(100, PLANES);
    k_fold<<<g2, 256>>>(images, out);
}

// round 7
// speedup vs baseline: 1.8507x; 1.5692x over previous
#include <cuda_runtime.h>

#define NPOS 1296
#define GRID1D 36
#define PP 7
#define NP 10
#define WINS 20
#define LL 14
#define HH 160
#define WW 160
#define PLANES 32
#define STEPS (NPOS*NP)   // 12960

// ---------------- scratch (static device globals; no runtime allocation) ----
__device__ float    g_M[49*49];              // Wp @ Wb
__device__ float    g_v[NP*49];              // (bp + pos_emb[n]) @ Wb + bb
__device__ float    g_den[(size_t)PLANES*STEPS*49]; // ~81 MB
__device__ unsigned g_rowsU[(size_t)PLANES*NPOS*3]; // row0 bytes, 4/u32, pad=200
__device__ unsigned g_colsU[(size_t)PLANES*NPOS*3]; // col0 bytes

// ---------------- K0: fuse the two projections (block per output row) --------
__global__ __launch_bounds__(64) void k_precompute(const float* __restrict__ Wp,
                                                   const float* __restrict__ bp,
                                                   const float* __restrict__ pe,
                                                   const float* __restrict__ Wb,
                                                   const float* __restrict__ bb) {
    const int row = blockIdx.x;   // 0..48 -> M rows, 49..58 -> v rows
    const int t = threadIdx.x;
    __shared__ float sRow[128];
    if (row < 49) {
        for (int e = t; e < 128; e += 64) sRow[e] = Wp[row*128 + e];
    } else {
        const int n = row - 49;
        for (int e = t; e < 128; e += 64) sRow[e] = bp[e] + pe[n*128 + e];
    }
    __syncthreads();
    for (int q = t; q < 49; q += 64) {
        float acc = (row < 49) ? 0.f : bb[q];
        #pragma unroll 8
        for (int e = 0; e < 128; e++) acc += sRow[e] * Wb[e*49 + q];
        if (row < 49) g_M[row*49 + q] = acc;
        else          g_v[(row-49)*49 + q] = acc;
    }
}

// ---------------- K1: conv + two-level top-10 + den + coord bytes -----------
__global__ __launch_bounds__(256) void k_stage1(const float* __restrict__ images) {
    const int pos   = blockIdx.x;
    const int plane = blockIdx.y;
    const int t     = threadIdx.x;

    const int ixp = pos / GRID1D;      // x outer
    const int iyp = pos % GRID1D;      // y inner
    const int x = ixp * 4, y = iyp * 4;
    const int xb0 = max(x - 7, 0), yb0 = max(y - 7, 0);
    const int winW = min(x + 13, WW) - xb0;
    const int winH = min(y + 13, HH) - yb0;

    __shared__ float sWin[WINS*WINS];
    __shared__ float sRef[49];
    __shared__ float sM[49*49];
    __shared__ float sV[NP*49];
    __shared__ unsigned long long sCand[70];
    __shared__ int   sSel[NP];
    __shared__ __align__(16) float sPT[49*12];   // transposed, padded patches
    __shared__ unsigned char sRow8[12], sCol8[12];

    const float* img = images + (size_t)plane * (HH*WW);
    for (int o = t; o < WINS*WINS; o += 256)
        sWin[o] = img[(yb0 + o / WINS) * WW + xb0 + o % WINS];
    if (t < 49) sRef[t] = img[(y + t / 7) * WW + x + t % 7];
    for (int o = t; o < 49*49; o += 256) sM[o] = g_M[o];
    for (int o = t; o < NP*49; o += 256) sV[o] = g_v[o];
    if (t < 70) sCand[t] = 0ull;
    __syncthreads();

    // per-thread sim value (196 outputs), invalid -> -inf
    const float NEG_INF = -__int_as_float(0x7f800000);
    unsigned long long key = 0ull;
    if (t < LL*LL) {
        const int i = t / LL, j = t % LL;
        float sim = NEG_INF;
        if (i <= winH - PP && j <= winW - PP) {
            float acc = 0.f;
            #pragma unroll
            for (int dy = 0; dy < PP; dy++)
                #pragma unroll
                for (int dx = 0; dx < PP; dx++)
                    acc += sWin[(i + dy)*WINS + j + dx] * sRef[dy*7 + dx];
            sim = acc;
        }
        const unsigned b = __float_as_uint(sim);
        const unsigned ord = (b & 0x80000000u) ? ~b : (b | 0x80000000u);
        key = ((unsigned long long)ord << 32) | (unsigned)(65535 - t);
    }
    // warp-local rank via shuffles (unique keys -> strict ordering)
    int wRank = 0;
    #pragma unroll
    for (int i = 0; i < 32; i++) {
        unsigned long long kj = __shfl_sync(0xffffffffu, key, i);
        wRank += (kj > key);
    }
    if (t < 196 && wRank < NP)
        sCand[(t >> 5) * NP + wRank] = key;
    __syncthreads();
    // final rank among <=70 candidates (superset of true top-10)
    if (t < 70) {
        const unsigned long long kc = sCand[t];
        int rank = 0;
        #pragma unroll 5
        for (int j = 0; j < 70; j++) rank += (sCand[j] > kc);
        if (rank < NP && kc)
            sSel[rank] = 65535 - (int)(kc & 0xffffu);
    }
    __syncthreads();

    // extract transposed patches into padded-transposed layout:
    // sPT[k*12 + n] = win[oy_n + k%7][ox_n + k/7]
    for (int o = t; o < 49*NP; o += 256) {
        int k = o / NP, n = o - k*NP;
        int id = sSel[n];
        int oy = id / LL, ox = id % LL;
        sPT[k*12 + n] = sWin[(oy + k % 7) * WINS + ox + k / 7];
    }
    // coord bytes (source bug preserved: row0 = col-offset + yb0, col0 = row-offset + xb0)
    if (t >= 64 && t < 64 + 12) {
        int n = t - 64;
        if (n < NP) {
            int id = sSel[n];
            int oy = id / LL, ox = id % LL;
            sRow8[n] = (unsigned char)(ox + yb0);
            sCol8[n] = (unsigned char)(oy + xb0);
        } else {
            sRow8[n] = 200; sCol8[n] = 200;   // pad: never matches
        }
    }
    __syncthreads();

    // den[n][q] = sum_k patchT[k][n] * M[k][q] + v[n][q]
    if (t < 49) {
        float a0=0.f,a1=0.f,a2=0.f,a3=0.f,a4=0.f,a5=0.f,a6=0.f,a7=0.f,a8=0.f,a9=0.f;
        const float4* P4 = (const float4*)sPT;
        #pragma unroll 7
        for (int k = 0; k < 49; k++) {
            const float m = sM[k*49 + t];
            const float4 pa = P4[k*3 + 0];
            const float4 pb = P4[k*3 + 1];
            const float4 pc = P4[k*3 + 2];
            a0 += m * pa.x; a1 += m * pa.y; a2 += m * pa.z; a3 += m * pa.w;
            a4 += m * pb.x; a5 += m * pb.y; a6 += m * pb.z; a7 += m * pb.w;
            a8 += m * pc.x; a9 += m * pc.y;
        }
        float* denOut = g_den + ((size_t)plane * STEPS + (size_t)pos * NP) * 49;
        denOut[0*49 + t] = a0 + sV[0*49 + t];
        denOut[1*49 + t] = a1 + sV[1*49 + t];
        denOut[2*49 + t] = a2 + sV[2*49 + t];
        denOut[3*49 + t] = a3 + sV[3*49 + t];
        denOut[4*49 + t] = a4 + sV[4*49 + t];
        denOut[5*49 + t] = a5 + sV[5*49 + t];
        denOut[6*49 + t] = a6 + sV[6*49 + t];
        denOut[7*49 + t] = a7 + sV[7*49 + t];
        denOut[8*49 + t] = a8 + sV[8*49 + t];
        denOut[9*49 + t] = a9 + sV[9*49 + t];
    }
    if (t >= 64 && t < 70) {
        int w = t - 64;               // 0..5
        int widx = w % 3;
        const unsigned char* src = (w < 3) ? sRow8 : sCol8;
        unsigned v = (unsigned)src[widx*4 + 0]
                   | ((unsigned)src[widx*4 + 1] << 8)
                   | ((unsigned)src[widx*4 + 2] << 16)
                   | ((unsigned)src[widx*4 + 3] << 24);
        unsigned* dst = (w < 3) ? g_rowsU : g_colsU;
        dst[((size_t)plane*NPOS + pos)*3 + widx] = v;
    }
}

// ---------------- K2: mask-table fold ----------------------------------------
__device__ __forceinline__ int flo(int c) { return (c <= 19) ? 0 : ((c - 9) >> 2); }
__device__ __forceinline__ int fhi(int c) { return min(GRID1D - 1, (c + 7) >> 2); }
__device__ __forceinline__ unsigned pack4(unsigned hm) {
    return ((hm & 0x01010101u) * 0x01020408u) >> 24;   // byte flags -> 4 bits
}
__device__ __forceinline__ unsigned mask10(unsigned vrep, const unsigned* p) {
    const unsigned seven = 0x07070707u;
    unsigned m0 = __vcmpltu4(__vsub4(vrep, p[0]), seven);
    unsigned m1 = __vcmpltu4(__vsub4(vrep, p[1]), seven);
    unsigned m2 = __vcmpltu4(__vsub4(vrep, p[2]), seven);
    return pack4(m0) | (pack4(m1) << 4) | (pack4(m2) << 8);
}

__global__ __launch_bounds__(256) void k_fold(const float* __restrict__ images,
                                              float* __restrict__ out) {
    const int plane = blockIdx.y;
    const int tile  = blockIdx.x;               // 0..99
    const int TR = (tile / 10) * 16, TC = (tile % 10) * 16;
    const int t = threadIdx.x;
    const int r  = TR + (t >> 4);
    const int cc = TC + (t & 15);

    const int Rlo = flo(TR), Rhi = fhi(TR + 15);
    const int Clo = flo(TC), Chi = fhi(TC + 15);
    const int rW = Rhi - Rlo + 1;               // <= 10
    const int cW = Chi - Clo + 1;               // <= 10
    const int nCell = rW * cW;                  // im and cnt rects have same count

    __shared__ unsigned sImR[100*3], sImC[100*3];   // im cells: ix-Clo major, iy-Rlo minor
    __shared__ unsigned sCnR[100*3], sCnC[100*3];   // cnt cells: ix-Rlo major, iy-Clo minor
    __shared__ unsigned short tRvR[100*16], tCvC[100*16]; // im masks
    __shared__ unsigned short tRvC[100*16], tCvR[100*16]; // cnt masks
    __shared__ float sRecip[96];

    for (int s = t; s < nCell*3; s += 256) {
        const int slot = s / 3, w = s - slot*3;
        const int ixo = slot / rW, iyo = slot - ixo*rW;
        const size_t g = ((size_t)plane*NPOS + (Clo + ixo)*GRID1D + (Rlo + iyo))*3 + w;
        sImR[s] = g_rowsU[g]; sImC[s] = g_colsU[g];
        const int ixo2 = slot / cW, iyo2 = slot - ixo2*cW;
        const size_t g2 = ((size_t)plane*NPOS + (Rlo + ixo2)*GRID1D + (Clo + iyo2))*3 + w;
        sCnR[s] = g_rowsU[g2]; sCnC[s] = g_colsU[g2];
    }
    if (t < 96) sRecip[t] = t ? (1.0f / (float)t) : 0.f;
    __syncthreads();

    for (int e = t; e < nCell*16; e += 256) {
        const int slot = e >> 4, i = e & 15;
        const unsigned rv = (unsigned)(TR + i) * 0x01010101u;
        const unsigned cv = (unsigned)(TC + i) * 0x01010101u;
        tRvR[e] = (unsigned short)mask10(rv, &sImR[slot*3]);
        tCvC[e] = (unsigned short)mask10(cv, &sImC[slot*3]);
        tRvC[e] = (unsigned short)mask10(rv, &sCnC[slot*3]);
        tCvR[e] = (unsigned short)mask10(cv, &sCnR[slot*3]);
    }
    __syncthreads();

    float val = images[(size_t)plane * (HH*WW) + r * WW + cc];

    // im role: ix in f(cc), iy in f(r).  cnt role: ix in f(r), iy in f(cc).
    const int imXLo = flo(cc), imXHi = fhi(cc);
    const int cnXLo = flo(r),  cnXHi = fhi(r);
    const int rp = r - TR, cp = cc - TC;
    const float* den = g_den + (size_t)plane * STEPS * 49;
    int pcnt = 1;

    const int xF = min(imXLo, cnXLo), xL = max(imXHi, cnXHi);
    const int xGap = max(imXLo, cnXLo);

    for (int ix = xF; ix <= xL; ix++) {
        const bool okIm = (ix >= imXLo) & (ix <= imXHi);
        const bool okCn = (ix >= cnXLo) & (ix <= cnXHi);
        if (!okIm && !okCn) { ix = xGap - 1; continue; }
        const int imRow = (ix - Clo) * rW;
        const int cnRow = (ix - Rlo) * cW;

        int yF, yL, yGap;
        if (okIm && okCn) { yF = xF; yL = xL; yGap = xGap; }
        else if (okIm)    { yF = cnXLo; yL = cnXHi; yGap = yF; }
        else              { yF = imXLo; yL = imXHi; yGap = yF; }

        for (int iy = yF; iy <= yL; iy++) {
            const bool hIm = okIm & (iy >= cnXLo) & (iy <= cnXHi);
            const bool hCn = okCn & (iy >= imXLo) & (iy <= imXHi);
            if (!hIm && !hCn) { iy = yGap - 1; continue; }
            unsigned maskIm = 0, maskCn = 0;
            int imSlot = 0;
            if (hIm) {
                imSlot = imRow + iy - Rlo;
                maskIm = (unsigned)tRvR[imSlot*16 + rp] & (unsigned)tCvC[imSlot*16 + cp];
            }
            if (hCn) {
                const int cnSlot = cnRow + iy - Clo;
                maskCn = (unsigned)tRvC[cnSlot*16 + rp] & (unsigned)tCvR[cnSlot*16 + cp];
            }
            if (maskIm) {
                const int stepBase = (ix*GRID1D + iy) * NP;
                unsigned m = maskIm;
                do {
                    const int n = __ffs(m) - 1; m &= m - 1;
                    const int cntNow = pcnt + __popc(maskCn & ((1u << n) - 1u));
                    const int row0 = (sImR[imSlot*3 + (n >> 2)] >> ((n & 3) * 8)) & 0xff;
                    const int col0 = (sImC[imSlot*3 + (n >> 2)] >> ((n & 3) * 8)) & 0xff;
                    const float d = __ldg(den + (size_t)(stepBase + n) * 49 + (r - row0)*7 + (cc - col0));
                    val = (val * (float)cntNow + d) * sRecip[cntNow + 1];
                } while (m);
            }
            pcnt += __popc(maskCn);
        }
    }
    out[(size_t)plane * (HH*WW) + r * WW + cc] = val;
}

// ---------------- launch ------------------------------------------------------
extern "C" void kernel_launch(void* const* d_in, const int* in_sizes, int n_in,
                              void* d_out, int out_size) {
    const float* images = (const float*)d_in[0];
    const float* Wp     = (const float*)d_in[1];
    const float* bp     = (const float*)d_in[2];
    const float* pe     = (const float*)d_in[3];
    const float* Wb     = (const float*)d_in[4];
    const float* bb     = (const float*)d_in[5];
    float* out = (float*)d_out;
    (void)in_sizes; (void)n_in; (void)out_size;

    k_precompute<<<59, 64>>>(Wp, bp, pe, Wb, bb);

    dim3 g1(NPOS, PLANES);
    k_stage1<<<g1, 256>>>(images);

    dim3 g2(100, PLANES);
    k_fold<<<g2, 256>>>(images, out);
}

// round 8
// speedup vs baseline: 1.9428x; 1.0498x over previous
#include <cuda_runtime.h>

#define NPOS 1296
#define GRID1D 36
#define PP 7
#define NP 10
#define WINS 20
#define LL 14
#define HH 160
#define WW 160
#define PLANES 32
#define STEPS (NPOS*NP)   // 12960

// ---------------- scratch (static device globals; no runtime allocation) ----
__device__ float    g_M[49*49];              // Wp @ Wb
__device__ float    g_v[NP*49];              // (bp + pos_emb[n]) @ Wb + bb
__device__ float    g_den[(size_t)PLANES*STEPS*49]; // ~81 MB
__device__ unsigned g_rowsU[(size_t)PLANES*NPOS*3]; // row0 bytes, 4/u32, pad=200
__device__ unsigned g_colsU[(size_t)PLANES*NPOS*3]; // col0 bytes

// ---------------- K0: fuse the two projections (block per output row) --------
__global__ __launch_bounds__(64) void k_precompute(const float* __restrict__ Wp,
                                                   const float* __restrict__ bp,
                                                   const float* __restrict__ pe,
                                                   const float* __restrict__ Wb,
                                                   const float* __restrict__ bb) {
    const int row = blockIdx.x;   // 0..48 -> M rows, 49..58 -> v rows
    const int t = threadIdx.x;
    __shared__ float sRow[128];
    if (row < 49) {
        for (int e = t; e < 128; e += 64) sRow[e] = Wp[row*128 + e];
    } else {
        const int n = row - 49;
        for (int e = t; e < 128; e += 64) sRow[e] = bp[e] + pe[n*128 + e];
    }
    __syncthreads();
    for (int q = t; q < 49; q += 64) {
        float acc = (row < 49) ? 0.f : bb[q];
        #pragma unroll 8
        for (int e = 0; e < 128; e++) acc += sRow[e] * Wb[e*49 + q];
        if (row < 49) g_M[row*49 + q] = acc;
        else          g_v[(row-49)*49 + q] = acc;
    }
}

// ---------------- K1: vec-conv + two-level top-10 + den + coord bytes -------
__global__ __launch_bounds__(256) void k_stage1(const float* __restrict__ images) {
    const int pos   = blockIdx.x;
    const int plane = blockIdx.y;
    const int t     = threadIdx.x;

    const int ixp = pos / GRID1D;      // x outer
    const int iyp = pos % GRID1D;      // y inner
    const int x = ixp * 4, y = iyp * 4;
    const int xb0 = max(x - 7, 0), yb0 = max(y - 7, 0);
    const int winW = min(x + 13, WW) - xb0;
    const int winH = min(y + 13, HH) - yb0;

    __shared__ __align__(16) float sWin[WINS*WINS];
    __shared__ float sRef[49];
    __shared__ unsigned long long sCand[70];
    __shared__ int   sSel[NP];
    __shared__ __align__(16) float sSim[196];
    __shared__ __align__(16) float sPT[49*12];   // transposed, padded patches
    __shared__ unsigned char sRow8[12], sCol8[12];

    const float* img = images + (size_t)plane * (HH*WW);
    for (int o = t; o < WINS*WINS; o += 256)
        sWin[o] = img[(yb0 + o / WINS) * WW + xb0 + o % WINS];
    if (t < 49) sRef[t] = img[(y + t / 7) * WW + x + t % 7];
    if (t < 70) sCand[t] = 0ull;
    __syncthreads();

    const float NEG_INF = -__int_as_float(0x7f800000);
    // vectorized conv: 56 threads, each (i, j4) computes 4 outputs j4..j4+3
    if (t < 56) {
        const int i = t >> 2, jq = t & 3;
        const int j4 = jq * 4;
        float a0 = 0.f, a1 = 0.f, a2 = 0.f, a3 = 0.f;
        const float4* w4 = (const float4*)sWin;
        #pragma unroll
        for (int dy = 0; dy < PP; dy++) {
            const int rb = (i + dy) * 5 + jq;
            const float4 A = w4[rb], B = w4[rb + 1], C = w4[rb + 2];
            const float wv[12] = {A.x,A.y,A.z,A.w,B.x,B.y,B.z,B.w,C.x,C.y,C.z,C.w};
            #pragma unroll
            for (int dx = 0; dx < PP; dx++) {
                const float rv = sRef[dy*7 + dx];
                a0 += wv[dx + 0] * rv;
                a1 += wv[dx + 1] * rv;
                a2 += wv[dx + 2] * rv;
                a3 += wv[dx + 3] * rv;
            }
        }
        const int iOK = (i <= winH - PP);
        const int jMax = winW - PP;
        sSim[i*LL + j4 + 0] = (iOK && j4 + 0 <= jMax) ? a0 : NEG_INF;
        sSim[i*LL + j4 + 1] = (iOK && j4 + 1 <= jMax) ? a1 : NEG_INF;
        if (j4 + 2 < LL) {
            sSim[i*LL + j4 + 2] = (iOK && j4 + 2 <= jMax) ? a2 : NEG_INF;
            sSim[i*LL + j4 + 3] = (iOK && j4 + 3 <= jMax) ? a3 : NEG_INF;
        }
    }
    __syncthreads();

    // warp-local rank via shuffles (unique keys -> strict ordering)
    unsigned long long key = 0ull;
    if (t < 196) {
        const unsigned b = __float_as_uint(sSim[t]);
        const unsigned ord = (b & 0x80000000u) ? ~b : (b | 0x80000000u);
        key = ((unsigned long long)ord << 32) | (unsigned)(65535 - t);
    }
    int wRank = 0;
    #pragma unroll
    for (int i = 0; i < 32; i++) {
        unsigned long long kj = __shfl_sync(0xffffffffu, key, i);
        wRank += (kj > key);
    }
    if (t < 196 && wRank < NP)
        sCand[(t >> 5) * NP + wRank] = key;
    __syncthreads();
    // final rank among <=70 candidates (superset of true top-10)
    if (t < 70) {
        const unsigned long long kc = sCand[t];
        int rank = 0;
        #pragma unroll 5
        for (int j = 0; j < 70; j++) rank += (sCand[j] > kc);
        if (rank < NP && kc)
            sSel[rank] = 65535 - (int)(kc & 0xffffu);
    }
    __syncthreads();

    // extract transposed patches into padded-transposed layout:
    // sPT[k*12 + n] = win[oy_n + k%7][ox_n + k/7]
    for (int o = t; o < 49*NP; o += 256) {
        int k = o / NP, n = o - k*NP;
        int id = sSel[n];
        int oy = id / LL, ox = id % LL;
        sPT[k*12 + n] = sWin[(oy + k % 7) * WINS + ox + k / 7];
    }
    // coord bytes (source bug preserved: row0 = col-offset + yb0, col0 = row-offset + xb0)
    if (t >= 64 && t < 64 + 12) {
        int n = t - 64;
        if (n < NP) {
            int id = sSel[n];
            int oy = id / LL, ox = id % LL;
            sRow8[n] = (unsigned char)(ox + yb0);
            sCol8[n] = (unsigned char)(oy + xb0);
        } else {
            sRow8[n] = 200; sCol8[n] = 200;   // pad: never matches
        }
    }
    __syncthreads();

    // den[n][q] = sum_k patchT[k][n] * M[k][q] + v[n][q]; M, v via L1 (hot)
    if (t < 49) {
        float a0=0.f,a1=0.f,a2=0.f,a3=0.f,a4=0.f,a5=0.f,a6=0.f,a7=0.f,a8=0.f,a9=0.f;
        const float4* P4 = (const float4*)sPT;
        #pragma unroll 7
        for (int k = 0; k < 49; k++) {
            const float m = __ldg(&g_M[k*49 + t]);
            const float4 pa = P4[k*3 + 0];
            const float4 pb = P4[k*3 + 1];
            const float4 pc = P4[k*3 + 2];
            a0 += m * pa.x; a1 += m * pa.y; a2 += m * pa.z; a3 += m * pa.w;
            a4 += m * pb.x; a5 += m * pb.y; a6 += m * pb.z; a7 += m * pb.w;
            a8 += m * pc.x; a9 += m * pc.y;
        }
        float* denOut = g_den + ((size_t)plane * STEPS + (size_t)pos * NP) * 49;
        denOut[0*49 + t] = a0 + __ldg(&g_v[0*49 + t]);
        denOut[1*49 + t] = a1 + __ldg(&g_v[1*49 + t]);
        denOut[2*49 + t] = a2 + __ldg(&g_v[2*49 + t]);
        denOut[3*49 + t] = a3 + __ldg(&g_v[3*49 + t]);
        denOut[4*49 + t] = a4 + __ldg(&g_v[4*49 + t]);
        denOut[5*49 + t] = a5 + __ldg(&g_v[5*49 + t]);
        denOut[6*49 + t] = a6 + __ldg(&g_v[6*49 + t]);
        denOut[7*49 + t] = a7 + __ldg(&g_v[7*49 + t]);
        denOut[8*49 + t] = a8 + __ldg(&g_v[8*49 + t]);
        denOut[9*49 + t] = a9 + __ldg(&g_v[9*49 + t]);
    }
    if (t >= 64 && t < 70) {
        int w = t - 64;               // 0..5
        int widx = w % 3;
        const unsigned char* src = (w < 3) ? sRow8 : sCol8;
        unsigned v = (unsigned)src[widx*4 + 0]
                   | ((unsigned)src[widx*4 + 1] << 8)
                   | ((unsigned)src[widx*4 + 2] << 16)
                   | ((unsigned)src[widx*4 + 3] << 24);
        unsigned* dst = (w < 3) ? g_rowsU : g_colsU;
        dst[((size_t)plane*NPOS + pos)*3 + widx] = v;
    }
}

// ---------------- K2: mask-table fold ----------------------------------------
__device__ __forceinline__ int flo(int c) { return (c <= 19) ? 0 : ((c - 9) >> 2); }
__device__ __forceinline__ int fhi(int c) { return min(GRID1D - 1, (c + 7) >> 2); }
__device__ __forceinline__ unsigned pack4(unsigned hm) {
    return ((hm & 0x01010101u) * 0x01020408u) >> 24;   // byte flags -> 4 bits
}
__device__ __forceinline__ unsigned mask10(unsigned vrep, const unsigned* p) {
    const unsigned seven = 0x07070707u;
    unsigned m0 = __vcmpltu4(__vsub4(vrep, p[0]), seven);
    unsigned m1 = __vcmpltu4(__vsub4(vrep, p[1]), seven);
    unsigned m2 = __vcmpltu4(__vsub4(vrep, p[2]), seven);
    return pack4(m0) | (pack4(m1) << 4) | (pack4(m2) << 8);
}

__global__ __launch_bounds__(256) void k_fold(const float* __restrict__ images,
                                              float* __restrict__ out) {
    const int plane = blockIdx.y;
    const int tile  = blockIdx.x;               // 0..99
    const int TR = (tile / 10) * 16, TC = (tile % 10) * 16;
    const int t = threadIdx.x;
    const int r  = TR + (t >> 4);
    const int cc = TC + (t & 15);

    const int Rlo = flo(TR), Rhi = fhi(TR + 15);
    const int Clo = flo(TC), Chi = fhi(TC + 15);
    const int rW = Rhi - Rlo + 1;               // <= 10
    const int cW = Chi - Clo + 1;               // <= 10
    const int nCell = rW * cW;                  // im and cnt rects have same count

    __shared__ unsigned sImR[100*3], sImC[100*3];   // im cells: ix-Clo major, iy-Rlo minor
    __shared__ unsigned sCnR[100*3], sCnC[100*3];   // cnt cells: ix-Rlo major, iy-Clo minor
    __shared__ unsigned short tRvR[100*16], tCvC[100*16]; // im masks
    __shared__ unsigned short tRvC[100*16], tCvR[100*16]; // cnt masks
    __shared__ float sRecip[96];

    for (int s = t; s < nCell*3; s += 256) {
        const int slot = s / 3, w = s - slot*3;
        const int ixo = slot / rW, iyo = slot - ixo*rW;
        const size_t g = ((size_t)plane*NPOS + (Clo + ixo)*GRID1D + (Rlo + iyo))*3 + w;
        sImR[s] = g_rowsU[g]; sImC[s] = g_colsU[g];
        const int ixo2 = slot / cW, iyo2 = slot - ixo2*cW;
        const size_t g2 = ((size_t)plane*NPOS + (Rlo + ixo2)*GRID1D + (Clo + iyo2))*3 + w;
        sCnR[s] = g_rowsU[g2]; sCnC[s] = g_colsU[g2];
    }
    if (t < 96) sRecip[t] = t ? (1.0f / (float)t) : 0.f;
    __syncthreads();

    for (int e = t; e < nCell*16; e += 256) {
        const int slot = e >> 4, i = e & 15;
        const unsigned rv = (unsigned)(TR + i) * 0x01010101u;
        const unsigned cv = (unsigned)(TC + i) * 0x01010101u;
        tRvR[e] = (unsigned short)mask10(rv, &sImR[slot*3]);
        tCvC[e] = (unsigned short)mask10(cv, &sImC[slot*3]);
        tRvC[e] = (unsigned short)mask10(rv, &sCnC[slot*3]);
        tCvR[e] = (unsigned short)mask10(cv, &sCnR[slot*3]);
    }
    __syncthreads();

    float val = images[(size_t)plane * (HH*WW) + r * WW + cc];

    // im role: ix in f(cc), iy in f(r).  cnt role: ix in f(r), iy in f(cc).
    const int imXLo = flo(cc), imXHi = fhi(cc);
    const int cnXLo = flo(r),  cnXHi = fhi(r);
    const int rp = r - TR, cp = cc - TC;
    const float* den = g_den + (size_t)plane * STEPS * 49;
    int pcnt = 1;

    const int xF = min(imXLo, cnXLo), xL = max(imXHi, cnXHi);
    const int xGap = max(imXLo, cnXLo);

    for (int ix = xF; ix <= xL; ix++) {
        const bool okIm = (ix >= imXLo) & (ix <= imXHi);
        const bool okCn = (ix >= cnXLo) & (ix <= cnXHi);
        if (!okIm && !okCn) { ix = xGap - 1; continue; }
        const int imRow = (ix - Clo) * rW;
        const int cnRow = (ix - Rlo) * cW;

        int yF, yL, yGap;
        if (okIm && okCn) { yF = xF; yL = xL; yGap = xGap; }
        else if (okIm)    { yF = cnXLo; yL = cnXHi; yGap = yF; }
        else              { yF = imXLo; yL = imXHi; yGap = yF; }

        for (int iy = yF; iy <= yL; iy++) {
            const bool hIm = okIm & (iy >= cnXLo) & (iy <= cnXHi);
            const bool hCn = okCn & (iy >= imXLo) & (iy <= imXHi);
            if (!hIm && !hCn) { iy = yGap - 1; continue; }
            unsigned maskIm = 0, maskCn = 0;
            int imSlot = 0;
            if (hIm) {
                imSlot = imRow + iy - Rlo;
                maskIm = (unsigned)tRvR[imSlot*16 + rp] & (unsigned)tCvC[imSlot*16 + cp];
            }
            if (hCn) {
                const int cnSlot = cnRow + iy - Clo;
                maskCn = (unsigned)tRvC[cnSlot*16 + rp] & (unsigned)tCvR[cnSlot*16 + cp];
            }
            if (maskIm) {
                const int stepBase = (ix*GRID1D + iy) * NP;
                unsigned m = maskIm;
                do {
                    const int n = __ffs(m) - 1; m &= m - 1;
                    const int cntNow = pcnt + __popc(maskCn & ((1u << n) - 1u));
                    const int row0 = (sImR[imSlot*3 + (n >> 2)] >> ((n & 3) * 8)) & 0xff;
                    const int col0 = (sImC[imSlot*3 + (n >> 2)] >> ((n & 3) * 8)) & 0xff;
                    const float d = __ldg(den + (size_t)(stepBase + n) * 49 + (r - row0)*7 + (cc - col0));
                    val = (val * (float)cntNow + d) * sRecip[cntNow + 1];
                } while (m);
            }
            pcnt += __popc(maskCn);
        }
    }
    out[(size_t)plane * (HH*WW) + r * WW + cc] = val;
}

// ---------------- launch ------------------------------------------------------
extern "C" void kernel_launch(void* const* d_in, const int* in_sizes, int n_in,
                              void* d_out, int out_size) {
    const float* images = (const float*)d_in[0];
    const float* Wp     = (const float*)d_in[1];
    const float* bp     = (const float*)d_in[2];
    const float* pe     = (const float*)d_in[3];
    const float* Wb     = (const float*)d_in[4];
    const float* bb     = (const float*)d_in[5];
    float* out = (float*)d_out;
    (void)in_sizes; (void)n_in; (void)out_size;

    k_precompute<<<59, 64>>>(Wp, bp, pe, Wb, bb);

    dim3 g1(NPOS, PLANES);
    k_stage1<<<g1, 256>>>(images);

    dim3 g2(100, PLANES);
    k_fold<<<g2, 256>>>(images, out);
}

// round 9
// speedup vs baseline: 2.3841x; 1.2272x over previous
#include <cuda_runtime.h>

#define NPOS 1296
#define GRID1D 36
#define PP 7
#define NP 10
#define WINS 20
#define LL 14
#define HH 160
#define WW 160
#define PLANES 32
#define STEPS (NPOS*NP)   // 12960

// ---------------- scratch (static device globals; no runtime allocation) ----
__device__ float    g_M[49*49];              // Wp @ Wb
__device__ float    g_v[NP*49];              // (bp + pos_emb[n]) @ Wb + bb
__device__ float    g_den[(size_t)PLANES*STEPS*49]; // ~81 MB
__device__ unsigned g_rowsU[(size_t)PLANES*NPOS*3]; // row0 bytes, 4/u32, pad=200
__device__ unsigned g_colsU[(size_t)PLANES*NPOS*3]; // col0 bytes

// ---------------- K0: fuse the two projections (block per output row) --------
__global__ __launch_bounds__(64) void k_precompute(const float* __restrict__ Wp,
                                                   const float* __restrict__ bp,
                                                   const float* __restrict__ pe,
                                                   const float* __restrict__ Wb,
                                                   const float* __restrict__ bb) {
    const int row = blockIdx.x;   // 0..48 -> M rows, 49..58 -> v rows
    const int t = threadIdx.x;
    __shared__ float sRow[128];
    if (row < 49) {
        for (int e = t; e < 128; e += 64) sRow[e] = Wp[row*128 + e];
    } else {
        const int n = row - 49;
        for (int e = t; e < 128; e += 64) sRow[e] = bp[e] + pe[n*128 + e];
    }
    __syncthreads();
    for (int q = t; q < 49; q += 64) {
        float acc = (row < 49) ? 0.f : bb[q];
        #pragma unroll 8
        for (int e = 0; e < 128; e++) acc += sRow[e] * Wb[e*49 + q];
        if (row < 49) g_M[row*49 + q] = acc;
        else          g_v[(row-49)*49 + q] = acc;
    }
}

// ---------------- K1: warp-per-(pos,plane) stage1 ----------------------------
__global__ __launch_bounds__(256) void k_stage1(const float* __restrict__ images) {
    const int warp = threadIdx.x >> 5;
    const int lane = threadIdx.x & 31;
    const int pos   = blockIdx.x * 8 + warp;
    const int plane = blockIdx.y;

    const int ixp = pos / GRID1D;      // x outer
    const int iyp = pos % GRID1D;      // y inner
    const int x = ixp * 4, y = iyp * 4;
    const int xb0 = max(x - 7, 0), yb0 = max(y - 7, 0);
    const int winW = min(x + 13, WW) - xb0;
    const int winH = min(y + 13, HH) - yb0;
    const int rx = x - xb0, ry = y - yb0;   // ref offset inside window

    __shared__ float sWinAll[8][400];
    __shared__ __align__(16) float sPTAll[8][588];   // 49 x 12 padded
    __shared__ int   sIdsAll[8][10];
    __shared__ int   sOffAll[8][10];
    float* sWin = sWinAll[warp];
    float* sPT  = sPTAll[warp];
    int*   sIds = sIdsAll[warp];
    int*   sOff = sOffAll[warp];

    const float* img = images + (size_t)plane * (HH*WW);
    #pragma unroll
    for (int o = lane; o < 400; o += 32)
        sWin[o] = img[(yb0 + o/20)*WW + xb0 + o%20];
    __syncwarp();

    // conv: output o = lane + 32m, results in registers
    float acc[7];
    int ii[7], jj[7];
    #pragma unroll
    for (int m = 0; m < 7; m++) {
        acc[m] = 0.f;
        const int oc = min(lane + 32*m, 195);
        ii[m] = oc / 14; jj[m] = oc % 14;
    }
    #pragma unroll
    for (int dy = 0; dy < 7; dy++) {
        float rv[7];
        #pragma unroll
        for (int dx = 0; dx < 7; dx++) rv[dx] = sWin[(ry + dy)*20 + rx + dx];
        #pragma unroll
        for (int m = 0; m < 7; m++) {
            const int base = (ii[m] + dy)*20 + jj[m];
            #pragma unroll
            for (int dx = 0; dx < 7; dx++)
                acc[m] += sWin[base + dx] * rv[dx];
        }
    }

    // build unique ordering keys
    const float NEG_INF = -__int_as_float(0x7f800000);
    unsigned long long keys[7];
    #pragma unroll
    for (int m = 0; m < 7; m++) {
        const int o = lane + 32*m;
        const float sim = (o < 196 && ii[m] <= winH - 7 && jj[m] <= winW - 7)
                        ? acc[m] : NEG_INF;
        const unsigned b = __float_as_uint(sim);
        const unsigned ord = (b & 0x80000000u) ? ~b : (b | 0x80000000u);
        keys[m] = (o < 196) ? (((unsigned long long)ord << 32) | (unsigned)(65535 - o))
                            : 0ull;
    }

    // exact top-10: 10 rounds of warp max-extraction (keys unique)
    int ids[10];
    #pragma unroll
    for (int r = 0; r < 10; r++) {
        unsigned long long best = keys[0];
        #pragma unroll
        for (int m = 1; m < 7; m++) if (keys[m] > best) best = keys[m];
        #pragma unroll
        for (int s = 16; s; s >>= 1) {
            const unsigned long long o2 = __shfl_xor_sync(0xffffffffu, best, s);
            if (o2 > best) best = o2;
        }
        const int id = 65535 - (int)(best & 0xffffu);
        ids[r] = id;
        if ((id & 31) == lane) {
            const int mw = id >> 5;
            #pragma unroll
            for (int mm = 0; mm < 7; mm++) if (mm == mw) keys[mm] = 0ull;
        }
    }
    if (lane == 0) {
        #pragma unroll
        for (int n = 0; n < 10; n++) {
            sIds[n] = ids[n];
            sOff[n] = (ids[n] / 14) * 20 + (ids[n] % 14);
        }
    }
    __syncwarp();

    // extract transposed patches: sPT[k*12+n] = win[oy+k%7][ox+k/7]
    for (int e = lane; e < 490; e += 32) {
        const int k = e / 10, n = e - k*10;
        sPT[k*12 + n] = sWin[sOff[n] + (k % 7)*20 + (k / 7)];
    }
    // coord words (source bug preserved: row0 = col-offset + yb0, col0 = row-offset + xb0)
    if (lane < 6) {
        const int w = lane;
        const int widx = (w < 3) ? w : w - 3;
        unsigned v = 0;
        #pragma unroll
        for (int p = 0; p < 4; p++) {
            const int nn = widx*4 + p;
            unsigned byte = 200;
            if (nn < 10) {
                const int id = sIds[nn];
                byte = (w < 3) ? (unsigned)(id % 14 + yb0)    // row0
                               : (unsigned)(id / 14 + xb0);   // col0
            }
            v |= byte << (p * 8);
        }
        unsigned* dst = (w < 3) ? g_rowsU : g_colsU;
        dst[((size_t)plane*NPOS + pos)*3 + widx] = v;
    }
    __syncwarp();

    // den[n][q] = sum_k patchT[k][n] * M[k][q] + v[n][q]
    float* denOut = g_den + ((size_t)plane * STEPS + (size_t)pos * NP) * 49;
    const float4* P4 = (const float4*)sPT;
    #pragma unroll
    for (int half = 0; half < 2; half++) {
        const int q = lane + 32*half;
        if (q < 49) {
            float a0=0.f,a1=0.f,a2=0.f,a3=0.f,a4=0.f,a5=0.f,a6=0.f,a7=0.f,a8=0.f,a9=0.f;
            #pragma unroll 7
            for (int k = 0; k < 49; k++) {
                const float m = __ldg(&g_M[k*49 + q]);
                const float4 pa = P4[k*3 + 0];
                const float4 pb = P4[k*3 + 1];
                const float4 pc = P4[k*3 + 2];
                a0 += m * pa.x; a1 += m * pa.y; a2 += m * pa.z; a3 += m * pa.w;
                a4 += m * pb.x; a5 += m * pb.y; a6 += m * pb.z; a7 += m * pb.w;
                a8 += m * pc.x; a9 += m * pc.y;
            }
            denOut[0*49 + q] = a0 + __ldg(&g_v[0*49 + q]);
            denOut[1*49 + q] = a1 + __ldg(&g_v[1*49 + q]);
            denOut[2*49 + q] = a2 + __ldg(&g_v[2*49 + q]);
            denOut[3*49 + q] = a3 + __ldg(&g_v[3*49 + q]);
            denOut[4*49 + q] = a4 + __ldg(&g_v[4*49 + q]);
            denOut[5*49 + q] = a5 + __ldg(&g_v[5*49 + q]);
            denOut[6*49 + q] = a6 + __ldg(&g_v[6*49 + q]);
            denOut[7*49 + q] = a7 + __ldg(&g_v[7*49 + q]);
            denOut[8*49 + q] = a8 + __ldg(&g_v[8*49 + q]);
            denOut[9*49 + q] = a9 + __ldg(&g_v[9*49 + q]);
        }
    }
}

// ---------------- K2: mask-table fold ----------------------------------------
__device__ __forceinline__ int flo(int c) { return (c <= 19) ? 0 : ((c - 9) >> 2); }
__device__ __forceinline__ int fhi(int c) { return min(GRID1D - 1, (c + 7) >> 2); }
__device__ __forceinline__ unsigned pack4(unsigned hm) {
    return ((hm & 0x01010101u) * 0x01020408u) >> 24;   // byte flags -> 4 bits
}
__device__ __forceinline__ unsigned mask10(unsigned vrep, const unsigned* p) {
    const unsigned seven = 0x07070707u;
    unsigned m0 = __vcmpltu4(__vsub4(vrep, p[0]), seven);
    unsigned m1 = __vcmpltu4(__vsub4(vrep, p[1]), seven);
    unsigned m2 = __vcmpltu4(__vsub4(vrep, p[2]), seven);
    return pack4(m0) | (pack4(m1) << 4) | (pack4(m2) << 8);
}

__global__ __launch_bounds__(256) void k_fold(const float* __restrict__ images,
                                              float* __restrict__ out) {
    const int plane = blockIdx.y;
    const int tile  = blockIdx.x;               // 0..99
    const int TR = (tile / 10) * 16, TC = (tile % 10) * 16;
    const int t = threadIdx.x;
    const int r  = TR + (t >> 4);
    const int cc = TC + (t & 15);

    const int Rlo = flo(TR), Rhi = fhi(TR + 15);
    const int Clo = flo(TC), Chi = fhi(TC + 15);
    const int rW = Rhi - Rlo + 1;               // <= 10
    const int cW = Chi - Clo + 1;               // <= 10
    const int nCell = rW * cW;                  // im and cnt rects have same count

    __shared__ unsigned sImR[100*3], sImC[100*3];   // im cells: ix-Clo major, iy-Rlo minor
    __shared__ unsigned sCnR[100*3], sCnC[100*3];   // cnt cells: ix-Rlo major, iy-Clo minor
    __shared__ unsigned short tRvR[100*16], tCvC[100*16]; // im masks
    __shared__ unsigned short tRvC[100*16], tCvR[100*16]; // cnt masks
    __shared__ float sRecip[96];

    for (int s = t; s < nCell*3; s += 256) {
        const int slot = s / 3, w = s - slot*3;
        const int ixo = slot / rW, iyo = slot - ixo*rW;
        const size_t g = ((size_t)plane*NPOS + (Clo + ixo)*GRID1D + (Rlo + iyo))*3 + w;
        sImR[s] = g_rowsU[g]; sImC[s] = g_colsU[g];
        const int ixo2 = slot / cW, iyo2 = slot - ixo2*cW;
        const size_t g2 = ((size_t)plane*NPOS + (Rlo + ixo2)*GRID1D + (Clo + iyo2))*3 + w;
        sCnR[s] = g_rowsU[g2]; sCnC[s] = g_colsU[g2];
    }
    if (t < 96) sRecip[t] = t ? (1.0f / (float)t) : 0.f;
    __syncthreads();

    for (int e = t; e < nCell*16; e += 256) {
        const int slot = e >> 4, i = e & 15;
        const unsigned rv = (unsigned)(TR + i) * 0x01010101u;
        const unsigned cv = (unsigned)(TC + i) * 0x01010101u;
        tRvR[e] = (unsigned short)mask10(rv, &sImR[slot*3]);
        tCvC[e] = (unsigned short)mask10(cv, &sImC[slot*3]);
        tRvC[e] = (unsigned short)mask10(rv, &sCnC[slot*3]);
        tCvR[e] = (unsigned short)mask10(cv, &sCnR[slot*3]);
    }
    __syncthreads();

    float val = images[(size_t)plane * (HH*WW) + r * WW + cc];

    // im role: ix in f(cc), iy in f(r).  cnt role: ix in f(r), iy in f(cc).
    const int imXLo = flo(cc), imXHi = fhi(cc);
    const int cnXLo = flo(r),  cnXHi = fhi(r);
    const int rp = r - TR, cp = cc - TC;
    const float* den = g_den + (size_t)plane * STEPS * 49;
    int pcnt = 1;

    const int xF = min(imXLo, cnXLo), xL = max(imXHi, cnXHi);
    const int xGap = max(imXLo, cnXLo);

    for (int ix = xF; ix <= xL; ix++) {
        const bool okIm = (ix >= imXLo) & (ix <= imXHi);
        const bool okCn = (ix >= cnXLo) & (ix <= cnXHi);
        if (!okIm && !okCn) { ix = xGap - 1; continue; }
        const int imRow = (ix - Clo) * rW;
        const int cnRow = (ix - Rlo) * cW;

        int yF, yL, yGap;
        if (okIm && okCn) { yF = xF; yL = xL; yGap = xGap; }
        else if (okIm)    { yF = cnXLo; yL = cnXHi; yGap = yF; }
        else              { yF = imXLo; yL = imXHi; yGap = yF; }

        for (int iy = yF; iy <= yL; iy++) {
            const bool hIm = okIm & (iy >= cnXLo) & (iy <= cnXHi);
            const bool hCn = okCn & (iy >= imXLo) & (iy <= imXHi);
            if (!hIm && !hCn) { iy = yGap - 1; continue; }
            unsigned maskIm = 0, maskCn = 0;
            int imSlot = 0;
            if (hIm) {
                imSlot = imRow + iy - Rlo;
                maskIm = (unsigned)tRvR[imSlot*16 + rp] & (unsigned)tCvC[imSlot*16 + cp];
            }
            if (hCn) {
                const int cnSlot = cnRow + iy - Clo;
                maskCn = (unsigned)tRvC[cnSlot*16 + rp] & (unsigned)tCvR[cnSlot*16 + cp];
            }
            if (maskIm) {
                const int stepBase = (ix*GRID1D + iy) * NP;
                unsigned m = maskIm;
                do {
                    const int n = __ffs(m) - 1; m &= m - 1;
                    const int cntNow = pcnt + __popc(maskCn & ((1u << n) - 1u));
                    const int row0 = (sImR[imSlot*3 + (n >> 2)] >> ((n & 3) * 8)) & 0xff;
                    const int col0 = (sImC[imSlot*3 + (n >> 2)] >> ((n & 3) * 8)) & 0xff;
                    const float d = __ldg(den + (size_t)(stepBase + n) * 49 + (r - row0)*7 + (cc - col0));
                    val = (val * (float)cntNow + d) * sRecip[cntNow + 1];
                } while (m);
            }
            pcnt += __popc(maskCn);
        }
    }
    out[(size_t)plane * (HH*WW) + r * WW + cc] = val;
}

// ---------------- launch ------------------------------------------------------
extern "C" void kernel_launch(void* const* d_in, const int* in_sizes, int n_in,
                              void* d_out, int out_size) {
    const float* images = (const float*)d_in[0];
    const float* Wp     = (const float*)d_in[1];
    const float* bp     = (const float*)d_in[2];
    const float* pe     = (const float*)d_in[3];
    const float* Wb     = (const float*)d_in[4];
    const float* bb     = (const float*)d_in[5];
    float* out = (float*)d_out;
    (void)in_sizes; (void)n_in; (void)out_size;

    k_precompute<<<59, 64>>>(Wp, bp, pe, Wb, bb);

    dim3 g1(162, PLANES);
    k_stage1<<<g1, 256>>>(images);

    dim3 g2(100, PLANES);
    k_fold<<<g2, 256>>>(images, out);
}

// round 10
// speedup vs baseline: 2.7033x; 1.1339x over previous
#include <cuda_runtime.h>

#define NPOS 1296
#define GRID1D 36
#define PP 7
#define NP 10
#define WINS 20
#define LL 14
#define HH 160
#define WW 160
#define PLANES 32
#define STEPS (NPOS*NP)   // 12960

// ---------------- scratch (static device globals; no runtime allocation) ----
__device__ float    g_M[49*49];              // Wp @ Wb
__device__ float    g_v[NP*49];              // (bp + pos_emb[n]) @ Wb + bb
__device__ float    g_den[(size_t)PLANES*STEPS*49]; // ~81 MB
__device__ unsigned g_rowsU[(size_t)PLANES*NPOS*3]; // row0 bytes, 4/u32, pad=200
__device__ unsigned g_colsU[(size_t)PLANES*NPOS*3]; // col0 bytes

// ---------------- K0: fuse the two projections (block per output row) --------
__global__ __launch_bounds__(64) void k_precompute(const float* __restrict__ Wp,
                                                   const float* __restrict__ bp,
                                                   const float* __restrict__ pe,
                                                   const float* __restrict__ Wb,
                                                   const float* __restrict__ bb) {
    const int row = blockIdx.x;   // 0..48 -> M rows, 49..58 -> v rows
    const int t = threadIdx.x;
    __shared__ float sRow[128];
    if (row < 49) {
        for (int e = t; e < 128; e += 64) sRow[e] = Wp[row*128 + e];
    } else {
        const int n = row - 49;
        for (int e = t; e < 128; e += 64) sRow[e] = bp[e] + pe[n*128 + e];
    }
    __syncthreads();
    for (int q = t; q < 49; q += 64) {
        float acc = (row < 49) ? 0.f : bb[q];
        #pragma unroll 8
        for (int e = 0; e < 128; e++) acc += sRow[e] * Wb[e*49 + q];
        if (row < 49) g_M[row*49 + q] = acc;
        else          g_v[(row-49)*49 + q] = acc;
    }
}

// ---------------- K1: warp-per-(pos,plane) stage1 ----------------------------
__global__ __launch_bounds__(256) void k_stage1(const float* __restrict__ images) {
    const int warp = threadIdx.x >> 5;
    const int lane = threadIdx.x & 31;
    const int pos   = blockIdx.x * 8 + warp;
    const int plane = blockIdx.y;

    const int ixp = pos / GRID1D;      // x outer
    const int iyp = pos % GRID1D;      // y inner
    const int x = ixp * 4, y = iyp * 4;
    const int xb0 = max(x - 7, 0), yb0 = max(y - 7, 0);
    const int winW = min(x + 13, WW) - xb0;
    const int winH = min(y + 13, HH) - yb0;
    const int rx = x - xb0, ry = y - yb0;   // ref offset inside window

    __shared__ float sWinAll[8][400];
    __shared__ __align__(16) float sPTAll[8][588];   // 49 x 12 padded
    __shared__ int   sIdsAll[8][10];
    __shared__ int   sOffAll[8][10];
    float* sWin = sWinAll[warp];
    float* sPT  = sPTAll[warp];
    int*   sIds = sIdsAll[warp];
    int*   sOff = sOffAll[warp];

    const float* img = images + (size_t)plane * (HH*WW);
    #pragma unroll
    for (int o = lane; o < 400; o += 32)
        sWin[o] = img[(yb0 + o/20)*WW + xb0 + o%20];
    __syncwarp();

    // sliding-window conv: lane -> (row i, half), 7 contiguous outputs each
    const int i  = min(lane >> 1, 13);     // 0..13
    const int hf = lane & 1;               // 0/1
    const int j0 = hf * 7;                 // 0 or 7
    float acc[7];
    #pragma unroll
    for (int m = 0; m < 7; m++) acc[m] = 0.f;
    #pragma unroll
    for (int dy = 0; dy < 7; dy++) {
        float w[13];
        const int rb = (i + dy)*20 + j0;
        #pragma unroll
        for (int c = 0; c < 13; c++) w[c] = sWin[rb + c];
        #pragma unroll
        for (int dx = 0; dx < 7; dx++) {
            const float rv = sWin[(ry + dy)*20 + rx + dx];
            #pragma unroll
            for (int m = 0; m < 7; m++)
                acc[m] += w[m + dx] * rv;
        }
    }

    // unique ordering keys; o = i*14 + j0 + m
    const float NEG_INF = -__int_as_float(0x7f800000);
    unsigned long long keys[7];
    #pragma unroll
    for (int m = 0; m < 7; m++) {
        const int j = j0 + m;
        const int o = i*14 + j;
        const float sim = (i <= winH - 7 && j <= winW - 7) ? acc[m] : NEG_INF;
        const unsigned b = __float_as_uint(sim);
        const unsigned ord = (b & 0x80000000u) ? ~b : (b | 0x80000000u);
        keys[m] = (lane < 28) ? (((unsigned long long)ord << 32) | (unsigned)(65535 - o))
                              : 0ull;
    }

    // exact top-10: 10 rounds of warp max-extraction (keys unique)
    int ids[10];
    #pragma unroll
    for (int r = 0; r < 10; r++) {
        unsigned long long best = keys[0];
        #pragma unroll
        for (int m = 1; m < 7; m++) if (keys[m] > best) best = keys[m];
        #pragma unroll
        for (int s = 16; s; s >>= 1) {
            const unsigned long long o2 = __shfl_xor_sync(0xffffffffu, best, s);
            if (o2 > best) best = o2;
        }
        const int id = 65535 - (int)(best & 0xffffu);
        ids[r] = id;
        const int bi = id / 14, bj = id % 14;
        const int ownLane = (bi << 1) | (bj >= 7);
        if (lane == ownLane) {
            const int mw = bj - ((bj >= 7) ? 7 : 0);
            #pragma unroll
            for (int mm = 0; mm < 7; mm++) if (mm == mw) keys[mm] = 0ull;
        }
    }
    if (lane == 0) {
        #pragma unroll
        for (int n = 0; n < 10; n++) {
            sIds[n] = ids[n];
            sOff[n] = (ids[n] / 14) * 20 + (ids[n] % 14);
        }
    }
    __syncwarp();

    // extract transposed patches: sPT[k*12+n] = win[oy+k%7][ox+k/7]
    for (int e = lane; e < 490; e += 32) {
        const int k = e / 10, n = e - k*10;
        sPT[k*12 + n] = sWin[sOff[n] + (k % 7)*20 + (k / 7)];
    }
    // coord words (source bug preserved: row0 = col-offset + yb0, col0 = row-offset + xb0)
    if (lane < 6) {
        const int w = lane;
        const int widx = (w < 3) ? w : w - 3;
        unsigned v = 0;
        #pragma unroll
        for (int p = 0; p < 4; p++) {
            const int nn = widx*4 + p;
            unsigned byte = 200;
            if (nn < 10) {
                const int id = sIds[nn];
                byte = (w < 3) ? (unsigned)(id % 14 + yb0)    // row0
                               : (unsigned)(id / 14 + xb0);   // col0
            }
            v |= byte << (p * 8);
        }
        unsigned* dst = (w < 3) ? g_rowsU : g_colsU;
        dst[((size_t)plane*NPOS + pos)*3 + widx] = v;
    }
    __syncwarp();

    // den[n][q] = sum_k patchT[k][n] * M[k][q] + v[n][q]
    // interleaved halves: q1 = lane, q2 = lane + 32 (lane < 17)
    {
        const int q1 = lane;
        const int q2 = lane + 32;
        const bool has2 = (q2 < 49);
        float a[10], b2[10];
        #pragma unroll
        for (int n = 0; n < 10; n++) { a[n] = 0.f; b2[n] = 0.f; }
        const float4* P4 = (const float4*)sPT;
        #pragma unroll 7
        for (int k = 0; k < 49; k++) {
            const float m1 = __ldg(&g_M[k*49 + q1]);
            const float m2 = has2 ? __ldg(&g_M[k*49 + q2]) : 0.f;
            const float4 pa = P4[k*3 + 0];
            const float4 pb = P4[k*3 + 1];
            const float4 pc = P4[k*3 + 2];
            a[0] += m1 * pa.x; b2[0] += m2 * pa.x;
            a[1] += m1 * pa.y; b2[1] += m2 * pa.y;
            a[2] += m1 * pa.z; b2[2] += m2 * pa.z;
            a[3] += m1 * pa.w; b2[3] += m2 * pa.w;
            a[4] += m1 * pb.x; b2[4] += m2 * pb.x;
            a[5] += m1 * pb.y; b2[5] += m2 * pb.y;
            a[6] += m1 * pb.z; b2[6] += m2 * pb.z;
            a[7] += m1 * pb.w; b2[7] += m2 * pb.w;
            a[8] += m1 * pc.x; b2[8] += m2 * pc.x;
            a[9] += m1 * pc.y; b2[9] += m2 * pc.y;
        }
        float* denOut = g_den + ((size_t)plane * STEPS + (size_t)pos * NP) * 49;
        #pragma unroll
        for (int n = 0; n < 10; n++) {
            denOut[n*49 + q1] = a[n] + __ldg(&g_v[n*49 + q1]);
            if (has2) denOut[n*49 + q2] = b2[n] + __ldg(&g_v[n*49 + q2]);
        }
    }
}

// ---------------- K2: mask-table fold ----------------------------------------
__device__ __forceinline__ int flo(int c) { return (c <= 19) ? 0 : ((c - 9) >> 2); }
__device__ __forceinline__ int fhi(int c) { return min(GRID1D - 1, (c + 7) >> 2); }
__device__ __forceinline__ unsigned pack4(unsigned hm) {
    return ((hm & 0x01010101u) * 0x01020408u) >> 24;   // byte flags -> 4 bits
}
__device__ __forceinline__ unsigned mask10(unsigned vrep, const unsigned* p) {
    const unsigned seven = 0x07070707u;
    unsigned m0 = __vcmpltu4(__vsub4(vrep, p[0]), seven);
    unsigned m1 = __vcmpltu4(__vsub4(vrep, p[1]), seven);
    unsigned m2 = __vcmpltu4(__vsub4(vrep, p[2]), seven);
    return pack4(m0) | (pack4(m1) << 4) | (pack4(m2) << 8);
}

__global__ __launch_bounds__(256) void k_fold(const float* __restrict__ images,
                                              float* __restrict__ out) {
    const int plane = blockIdx.y;
    const int tile  = blockIdx.x;               // 0..99
    const int TR = (tile / 10) * 16, TC = (tile % 10) * 16;
    const int t = threadIdx.x;
    const int r  = TR + (t >> 4);
    const int cc = TC + (t & 15);

    const int Rlo = flo(TR), Rhi = fhi(TR + 15);
    const int Clo = flo(TC), Chi = fhi(TC + 15);
    const int rW = Rhi - Rlo + 1;               // <= 10
    const int cW = Chi - Clo + 1;               // <= 10
    const int nCell = rW * cW;                  // im and cnt rects have same count

    __shared__ unsigned sImR[100*3], sImC[100*3];   // im cells: ix-Clo major, iy-Rlo minor
    __shared__ unsigned sCnR[100*3], sCnC[100*3];   // cnt cells: ix-Rlo major, iy-Clo minor
    __shared__ unsigned short tRvR[100*16], tCvC[100*16]; // im masks
    __shared__ unsigned short tRvC[100*16], tCvR[100*16]; // cnt masks
    __shared__ float sRecip[96];

    for (int s = t; s < nCell*3; s += 256) {
        const int slot = s / 3, w = s - slot*3;
        const int ixo = slot / rW, iyo = slot - ixo*rW;
        const size_t g = ((size_t)plane*NPOS + (Clo + ixo)*GRID1D + (Rlo + iyo))*3 + w;
        sImR[s] = g_rowsU[g]; sImC[s] = g_colsU[g];
        const int ixo2 = slot / cW, iyo2 = slot - ixo2*cW;
        const size_t g2 = ((size_t)plane*NPOS + (Rlo + ixo2)*GRID1D + (Clo + iyo2))*3 + w;
        sCnR[s] = g_rowsU[g2]; sCnC[s] = g_colsU[g2];
    }
    if (t < 96) sRecip[t] = t ? (1.0f / (float)t) : 0.f;
    __syncthreads();

    for (int e = t; e < nCell*16; e += 256) {
        const int slot = e >> 4, i = e & 15;
        const unsigned rv = (unsigned)(TR + i) * 0x01010101u;
        const unsigned cv = (unsigned)(TC + i) * 0x01010101u;
        tRvR[e] = (unsigned short)mask10(rv, &sImR[slot*3]);
        tCvC[e] = (unsigned short)mask10(cv, &sImC[slot*3]);
        tRvC[e] = (unsigned short)mask10(rv, &sCnC[slot*3]);
        tCvR[e] = (unsigned short)mask10(cv, &sCnR[slot*3]);
    }
    __syncthreads();

    float val = images[(size_t)plane * (HH*WW) + r * WW + cc];

    // im role: ix in f(cc), iy in f(r).  cnt role: ix in f(r), iy in f(cc).
    const int imXLo = flo(cc), imXHi = fhi(cc);
    const int cnXLo = flo(r),  cnXHi = fhi(r);
    const int rp = r - TR, cp = cc - TC;
    const float* den = g_den + (size_t)plane * STEPS * 49;
    int pcnt = 1;

    const int xF = min(imXLo, cnXLo), xL = max(imXHi, cnXHi);
    const int xGap = max(imXLo, cnXLo);

    for (int ix = xF; ix <= xL; ix++) {
        const bool okIm = (ix >= imXLo) & (ix <= imXHi);
        const bool okCn = (ix >= cnXLo) & (ix <= cnXHi);
        if (!okIm && !okCn) { ix = xGap - 1; continue; }
        const int imRow = (ix - Clo) * rW;
        const int cnRow = (ix - Rlo) * cW;

        int yF, yL, yGap;
        if (okIm && okCn) { yF = xF; yL = xL; yGap = xGap; }
        else if (okIm)    { yF = cnXLo; yL = cnXHi; yGap = yF; }
        else              { yF = imXLo; yL = imXHi; yGap = yF; }

        for (int iy = yF; iy <= yL; iy++) {
            const bool hIm = okIm & (iy >= cnXLo) & (iy <= cnXHi);
            const bool hCn = okCn & (iy >= imXLo) & (iy <= imXHi);
            if (!hIm && !hCn) { iy = yGap - 1; continue; }
            unsigned maskIm = 0, maskCn = 0;
            int imSlot = 0;
            if (hIm) {
                imSlot = imRow + iy - Rlo;
                maskIm = (unsigned)tRvR[imSlot*16 + rp] & (unsigned)tCvC[imSlot*16 + cp];
            }
            if (hCn) {
                const int cnSlot = cnRow + iy - Clo;
                maskCn = (unsigned)tRvC[cnSlot*16 + rp] & (unsigned)tCvR[cnSlot*16 + cp];
            }
            if (maskIm) {
                const int stepBase = (ix*GRID1D + iy) * NP;
                unsigned m = maskIm;
                do {
                    const int n = __ffs(m) - 1; m &= m - 1;
                    const int cntNow = pcnt + __popc(maskCn & ((1u << n) - 1u));
                    const int row0 = (sImR[imSlot*3 + (n >> 2)] >> ((n & 3) * 8)) & 0xff;
                    const int col0 = (sImC[imSlot*3 + (n >> 2)] >> ((n & 3) * 8)) & 0xff;
                    const float d = __ldg(den + (size_t)(stepBase + n) * 49 + (r - row0)*7 + (cc - col0));
                    val = (val * (float)cntNow + d) * sRecip[cntNow + 1];
                } while (m);
            }
            pcnt += __popc(maskCn);
        }
    }
    out[(size_t)plane * (HH*WW) + r * WW + cc] = val;
}

// ---------------- launch ------------------------------------------------------
extern "C" void kernel_launch(void* const* d_in, const int* in_sizes, int n_in,
                              void* d_out, int out_size) {
    const float* images = (const float*)d_in[0];
    const float* Wp     = (const float*)d_in[1];
    const float* bp     = (const float*)d_in[2];
    const float* pe     = (const float*)d_in[3];
    const float* Wb     = (const float*)d_in[4];
    const float* bb     = (const float*)d_in[5];
    float* out = (float*)d_out;
    (void)in_sizes; (void)n_in; (void)out_size;

    k_precompute<<<59, 64>>>(Wp, bp, pe, Wb, bb);

    dim3 g1(162, PLANES);
    k_stage1<<<g1, 256>>>(images);

    dim3 g2(100, PLANES);
    k_fold<<<g2, 256>>>(images, out);
}

// round 12
// speedup vs baseline: 2.8870x; 1.0680x over previous
#include <cuda_runtime.h>

#define NPOS 1296
#define GRID1D 36
#define PP 7
#define NP 10
#define WINS 20
#define LL 14
#define HH 160
#define WW 160
#define PLANES 32
#define STEPS (NPOS*NP)   // 12960

// ---------------- scratch (static device globals; no runtime allocation) ----
__device__ float    g_M[49*49];              // Wp @ Wb
__device__ float    g_v[NP*49];              // (bp + pos_emb[n]) @ Wb + bb
__device__ float    g_den[(size_t)PLANES*STEPS*49]; // ~81 MB
__device__ unsigned g_rowsU[(size_t)PLANES*NPOS*3]; // row0 bytes, 4/u32, pad=200
__device__ unsigned g_colsU[(size_t)PLANES*NPOS*3]; // col0 bytes

// ---------------- K0: fuse the two projections (block per output row) --------
__global__ __launch_bounds__(64) void k_precompute(const float* __restrict__ Wp,
                                                   const float* __restrict__ bp,
                                                   const float* __restrict__ pe,
                                                   const float* __restrict__ Wb,
                                                   const float* __restrict__ bb) {
    const int row = blockIdx.x;   // 0..48 -> M rows, 49..58 -> v rows
    const int t = threadIdx.x;
    __shared__ float sRow[128];
    if (row < 49) {
        for (int e = t; e < 128; e += 64) sRow[e] = Wp[row*128 + e];
    } else {
        const int n = row - 49;
        for (int e = t; e < 128; e += 64) sRow[e] = bp[e] + pe[n*128 + e];
    }
    __syncthreads();
    for (int q = t; q < 49; q += 64) {
        float acc = (row < 49) ? 0.f : bb[q];
        #pragma unroll 8
        for (int e = 0; e < 128; e++) acc += sRow[e] * Wb[e*49 + q];
        if (row < 49) g_M[row*49 + q] = acc;
        else          g_v[(row-49)*49 + q] = acc;
    }
}

// ---------------- K1: warp-per-(pos,plane) stage1 ----------------------------
__global__ __launch_bounds__(256) void k_stage1(const float* __restrict__ images) {
    const int warp = threadIdx.x >> 5;
    const int lane = threadIdx.x & 31;
    const int pos   = blockIdx.x * 8 + warp;
    const int plane = blockIdx.y;

    const int ixp = pos / GRID1D;      // x outer
    const int iyp = pos % GRID1D;      // y inner
    const int x = ixp * 4, y = iyp * 4;
    const int xb0 = max(x - 7, 0), yb0 = max(y - 7, 0);
    const int winW = min(x + 13, WW) - xb0;
    const int winH = min(y + 13, HH) - yb0;
    const int rx = x - xb0, ry = y - yb0;   // ref offset inside window

    __shared__ float sWinAll[8][400];
    __shared__ __align__(16) float sPTAll[8][588];   // 49 x 12 padded
    __shared__ int   sIdsAll[8][10];
    __shared__ int   sOffAll[8][10];
    float* sWin = sWinAll[warp];
    float* sPT  = sPTAll[warp];
    int*   sIds = sIdsAll[warp];
    int*   sOff = sOffAll[warp];

    const float* img = images + (size_t)plane * (HH*WW);
    #pragma unroll
    for (int o = lane; o < 400; o += 32)
        sWin[o] = img[(yb0 + o/20)*WW + xb0 + o%20];
    __syncwarp();

    // sliding-window conv: lane -> (row i, half), 7 contiguous outputs each
    const int i  = min(lane >> 1, 13);     // 0..13
    const int hf = lane & 1;               // 0/1
    const int j0 = hf * 7;                 // 0 or 7
    float acc[7];
    #pragma unroll
    for (int m = 0; m < 7; m++) acc[m] = 0.f;
    #pragma unroll
    for (int dy = 0; dy < 7; dy++) {
        float w[13];
        const int rb = (i + dy)*20 + j0;
        #pragma unroll
        for (int c = 0; c < 13; c++) w[c] = sWin[rb + c];
        #pragma unroll
        for (int dx = 0; dx < 7; dx++) {
            const float rv = sWin[(ry + dy)*20 + rx + dx];
            #pragma unroll
            for (int m = 0; m < 7; m++)
                acc[m] += w[m + dx] * rv;
        }
    }

    // unique ordering keys; o = i*14 + j0 + m
    const float NEG_INF = -__int_as_float(0x7f800000);
    unsigned long long keys[7];
    #pragma unroll
    for (int m = 0; m < 7; m++) {
        const int j = j0 + m;
        const int o = i*14 + j;
        const float sim = (i <= winH - 7 && j <= winW - 7) ? acc[m] : NEG_INF;
        const unsigned b = __float_as_uint(sim);
        const unsigned ord = (b & 0x80000000u) ? ~b : (b | 0x80000000u);
        keys[m] = (lane < 28) ? (((unsigned long long)ord << 32) | (unsigned)(65535 - o))
                              : 0ull;
    }

    // exact top-10: 10 rounds of warp max-extraction (keys unique)
    int ids[10];
    #pragma unroll
    for (int r = 0; r < 10; r++) {
        unsigned long long best = keys[0];
        #pragma unroll
        for (int m = 1; m < 7; m++) if (keys[m] > best) best = keys[m];
        #pragma unroll
        for (int s = 16; s; s >>= 1) {
            const unsigned long long o2 = __shfl_xor_sync(0xffffffffu, best, s);
            if (o2 > best) best = o2;
        }
        const int id = 65535 - (int)(best & 0xffffu);
        ids[r] = id;
        const int bi = id / 14, bj = id % 14;
        const int ownLane = (bi << 1) | (bj >= 7);
        if (lane == ownLane) {
            const int mw = bj - ((bj >= 7) ? 7 : 0);
            #pragma unroll
            for (int mm = 0; mm < 7; mm++) if (mm == mw) keys[mm] = 0ull;
        }
    }
    if (lane == 0) {
        #pragma unroll
        for (int n = 0; n < 10; n++) {
            sIds[n] = ids[n];
            sOff[n] = (ids[n] / 14) * 20 + (ids[n] % 14);
        }
    }
    __syncwarp();

    // extract transposed patches: sPT[k*12+n] = win[oy+k%7][ox+k/7]
    for (int e = lane; e < 490; e += 32) {
        const int k = e / 10, n = e - k*10;
        sPT[k*12 + n] = sWin[sOff[n] + (k % 7)*20 + (k / 7)];
    }
    // coord words (source bug preserved: row0 = col-offset + yb0, col0 = row-offset + xb0)
    if (lane < 6) {
        const int w = lane;
        const int widx = (w < 3) ? w : w - 3;
        unsigned v = 0;
        #pragma unroll
        for (int p = 0; p < 4; p++) {
            const int nn = widx*4 + p;
            unsigned byte = 200;
            if (nn < 10) {
                const int id = sIds[nn];
                byte = (w < 3) ? (unsigned)(id % 14 + yb0)    // row0
                               : (unsigned)(id / 14 + xb0);   // col0
            }
            v |= byte << (p * 8);
        }
        unsigned* dst = (w < 3) ? g_rowsU : g_colsU;
        dst[((size_t)plane*NPOS + pos)*3 + widx] = v;
    }
    __syncwarp();

    // den[n][q] = sum_k patchT[k][n] * M[k][q] + v[n][q]
    // interleaved halves: q1 = lane, q2 = lane + 32 (lane < 17)
    {
        const int q1 = lane;
        const int q2 = lane + 32;
        const bool has2 = (q2 < 49);
        float a[10], b2[10];
        #pragma unroll
        for (int n = 0; n < 10; n++) { a[n] = 0.f; b2[n] = 0.f; }
        const float4* P4 = (const float4*)sPT;
        #pragma unroll 7
        for (int k = 0; k < 49; k++) {
            const float m1 = __ldg(&g_M[k*49 + q1]);
            const float m2 = has2 ? __ldg(&g_M[k*49 + q2]) : 0.f;
            const float4 pa = P4[k*3 + 0];
            const float4 pb = P4[k*3 + 1];
            const float4 pc = P4[k*3 + 2];
            a[0] += m1 * pa.x; b2[0] += m2 * pa.x;
            a[1] += m1 * pa.y; b2[1] += m2 * pa.y;
            a[2] += m1 * pa.z; b2[2] += m2 * pa.z;
            a[3] += m1 * pa.w; b2[3] += m2 * pa.w;
            a[4] += m1 * pb.x; b2[4] += m2 * pb.x;
            a[5] += m1 * pb.y; b2[5] += m2 * pb.y;
            a[6] += m1 * pb.z; b2[6] += m2 * pb.z;
            a[7] += m1 * pb.w; b2[7] += m2 * pb.w;
            a[8] += m1 * pc.x; b2[8] += m2 * pc.x;
            a[9] += m1 * pc.y; b2[9] += m2 * pc.y;
        }
        float* denOut = g_den + ((size_t)plane * STEPS + (size_t)pos * NP) * 49;
        #pragma unroll
        for (int n = 0; n < 10; n++) {
            denOut[n*49 + q1] = a[n] + __ldg(&g_v[n*49 + q1]);
            if (has2) denOut[n*49 + q2] = b2[n] + __ldg(&g_v[n*49 + q2]);
        }
    }
}

// ---------------- K2: role-split mask-table fold ------------------------------
__device__ __forceinline__ int flo(int c) { return (c <= 19) ? 0 : ((c - 9) >> 2); }
__device__ __forceinline__ int fhi(int c) { return min(GRID1D - 1, (c + 7) >> 2); }
__device__ __forceinline__ unsigned pack4(unsigned hm) {
    return ((hm & 0x01010101u) * 0x01020408u) >> 24;   // byte flags -> 4 bits
}
__device__ __forceinline__ unsigned mask10(unsigned vrep, const unsigned* p) {
    const unsigned seven = 0x07070707u;
    unsigned m0 = __vcmpltu4(__vsub4(vrep, p[0]), seven);
    unsigned m1 = __vcmpltu4(__vsub4(vrep, p[1]), seven);
    unsigned m2 = __vcmpltu4(__vsub4(vrep, p[2]), seven);
    return pack4(m0) | (pack4(m1) << 4) | (pack4(m2) << 8);
}

__global__ __launch_bounds__(256) void k_fold(const float* __restrict__ images,
                                              float* __restrict__ out) {
    const int plane = blockIdx.y;
    const int tile  = blockIdx.x;               // 0..99
    const int TR = (tile / 10) * 16, TC = (tile % 10) * 16;
    const int t = threadIdx.x;
    const int r  = TR + (t >> 4);
    const int cc = TC + (t & 15);

    const int Rlo = flo(TR), Rhi = fhi(TR + 15);
    const int Clo = flo(TC), Chi = fhi(TC + 15);
    const int rW = Rhi - Rlo + 1;               // <= 10
    const int cW = Chi - Clo + 1;               // <= 10
    const int nCell = rW * cW;                  // im and cnt rects have same count

    __shared__ unsigned sImR[100*3], sImC[100*3];   // im cells: ix-Clo major, iy-Rlo minor
    __shared__ unsigned sCnR[100*3], sCnC[100*3];   // cnt cells: ix-Rlo major, iy-Clo minor
    __shared__ unsigned short tRvR[100*16], tCvC[100*16]; // im masks
    __shared__ unsigned short tRvC[100*16], tCvR[100*16]; // cnt masks
    __shared__ float sRecip[96];

    for (int s = t; s < nCell*3; s += 256) {
        const int slot = s / 3, w = s - slot*3;
        const int ixo = slot / rW, iyo = slot - ixo*rW;
        const size_t g = ((size_t)plane*NPOS + (Clo + ixo)*GRID1D + (Rlo + iyo))*3 + w;
        sImR[s] = g_rowsU[g]; sImC[s] = g_colsU[g];
        const int ixo2 = slot / cW, iyo2 = slot - ixo2*cW;
        const size_t g2 = ((size_t)plane*NPOS + (Rlo + ixo2)*GRID1D + (Clo + iyo2))*3 + w;
        sCnR[s] = g_rowsU[g2]; sCnC[s] = g_colsU[g2];
    }
    if (t < 96) sRecip[t] = t ? (1.0f / (float)t) : 0.f;
    __syncthreads();

    for (int e = t; e < nCell*16; e += 256) {
        const int slot = e >> 4, i = e & 15;
        const unsigned rv = (unsigned)(TR + i) * 0x01010101u;
        const unsigned cv = (unsigned)(TC + i) * 0x01010101u;
        tRvR[e] = (unsigned short)mask10(rv, &sImR[slot*3]);
        tCvC[e] = (unsigned short)mask10(cv, &sImC[slot*3]);
        tRvC[e] = (unsigned short)mask10(rv, &sCnC[slot*3]);
        tCvR[e] = (unsigned short)mask10(cv, &sCnR[slot*3]);
    }
    __syncthreads();

    float val = images[(size_t)plane * (HH*WW) + r * WW + cc];

    // im role: ix in f(cc), iy in f(r).  cnt role: ix in f(r), iy in f(cc).
    const int imXLo = flo(cc), imXHi = fhi(cc);
    const int cnXLo = flo(r),  cnXHi = fhi(r);
    const int rp = r - TR, cp = cc - TC;
    const float* den = g_den + (size_t)plane * STEPS * 49;

    if (imXLo <= imXHi && cnXLo <= cnXHi) {
        const bool cntFirst = (cnXHi < imXLo);
        const bool imFirst  = (imXHi < cnXLo);
        if (cntFirst | imFirst) {
            // ---- disjoint ranges: constant count for every im hit ----
            int tot = 0;
            if (cntFirst) {
                for (int ix = cnXLo; ix <= cnXHi; ix++) {
                    const int base = (ix - Rlo) * cW;
                    #pragma unroll 3
                    for (int iy = imXLo; iy <= imXHi; iy++) {
                        const int slot = base + iy - Clo;
                        tot += __popc((unsigned)tRvC[slot*16 + rp] &
                                      (unsigned)tCvR[slot*16 + cp]);
                    }
                }
            }
            const int c = 1 + tot;
            const float G = sRecip[c + 1];
            const float F = (float)c * G;
            for (int ix = imXLo; ix <= imXHi; ix++) {
                const int imRow = (ix - Clo) * rW;
                #pragma unroll 3
                for (int iy = cnXLo; iy <= cnXHi; iy++) {
                    const int slot = imRow + iy - Rlo;
                    unsigned m = (unsigned)tRvR[slot*16 + rp] &
                                 (unsigned)tCvC[slot*16 + cp];
                    if (m) {
                        const int stepBase = (ix*GRID1D + iy) * NP;
                        do {
                            const int n = __ffs(m) - 1; m &= m - 1;
                            const int row0 = (sImR[slot*3 + (n >> 2)] >> ((n & 3)*8)) & 0xff;
                            const int col0 = (sImC[slot*3 + (n >> 2)] >> ((n & 3)*8)) & 0xff;
                            const float d = __ldg(den + (size_t)(stepBase + n)*49
                                                      + (r - row0)*7 + (cc - col0));
                            val = val * F + d * G;
                        } while (m);
                    }
                }
            }
        } else {
            // ---- overlapping ranges: merged step-ordered scan ----
            int pcnt = 1;
            const int xF = min(imXLo, cnXLo), xL = max(imXHi, cnXHi);
            for (int ix = xF; ix <= xL; ix++) {
                const bool okIm = (ix >= imXLo) & (ix <= imXHi);
                const bool okCn = (ix >= cnXLo) & (ix <= cnXHi);
                const int imRow = (ix - Clo) * rW;
                const int cnRow = (ix - Rlo) * cW;
                for (int iy = xF; iy <= xL; iy++) {
                    const bool hIm = okIm & (iy >= cnXLo) & (iy <= cnXHi);
                    const bool hCn = okCn & (iy >= imXLo) & (iy <= imXHi);
                    if (!hIm && !hCn) continue;
                    unsigned maskIm = 0, maskCn = 0;
                    int imSlot = 0;
                    if (hIm) {
                        imSlot = imRow + iy - Rlo;
                        maskIm = (unsigned)tRvR[imSlot*16 + rp] &
                                 (unsigned)tCvC[imSlot*16 + cp];
                    }
                    if (hCn) {
                        const int cnSlot = cnRow + iy - Clo;
                        maskCn = (unsigned)tRvC[cnSlot*16 + rp] &
                                 (unsigned)tCvR[cnSlot*16 + cp];
                    }
                    if (maskIm) {
                        const int stepBase = (ix*GRID1D + iy) * NP;
                        unsigned m = maskIm;
                        do {
                            const int n = __ffs(m) - 1; m &= m - 1;
                            const int cntNow = pcnt + __popc(maskCn & ((1u << n) - 1u));
                            const int row0 = (sImR[imSlot*3 + (n >> 2)] >> ((n & 3)*8)) & 0xff;
                            const int col0 = (sImC[imSlot*3 + (n >> 2)] >> ((n & 3)*8)) & 0xff;
                            const float d = __ldg(den + (size_t)(stepBase + n)*49
                                                      + (r - row0)*7 + (cc - col0));
                            val = (val * (float)cntNow + d) * sRecip[cntNow + 1];
                        } while (m);
                    }
                    pcnt += __popc(maskCn);
                }
            }
        }
    }
    out[(size_t)plane * (HH*WW) + r * WW + cc] = val;
}

// ---------------- launch ------------------------------------------------------
extern "C" void kernel_launch(void* const* d_in, const int* in_sizes, int n_in,
                              void* d_out, int out_size) {
    const float* images = (const float*)d_in[0];
    const float* Wp     = (const float*)d_in[1];
    const float* bp     = (const float*)d_in[2];
    const float* pe     = (const float*)d_in[3];
    const float* Wb     = (const float*)d_in[4];
    const float* bb     = (const float*)d_in[5];
    float* out = (float*)d_out;
    (void)in_sizes; (void)n_in; (void)out_size;

    k_precompute<<<59, 64>>>(Wp, bp, pe, Wb, bb);

    dim3 g1(162, PLANES);
    k_stage1<<<g1, 256>>>(images);

    dim3 g2(100, PLANES);
    k_fold<<<g2, 256>>>(images, out);
}

// round 13
// speedup vs baseline: 2.9520x; 1.0225x over previous
#include <cuda_runtime.h>

#define NPOS 1296
#define GRID1D 36
#define PP 7
#define NP 10
#define WINS 20
#define LL 14
#define HH 160
#define WW 160
#define PLANES 32
#define STEPS (NPOS*NP)   // 12960

// ---------------- scratch (static device globals; no runtime allocation) ----
__device__ float    g_M[49*49];              // Wp @ Wb
__device__ float    g_v[NP*49];              // (bp + pos_emb[n]) @ Wb + bb
__device__ float    g_den[(size_t)PLANES*STEPS*49]; // ~81 MB
__device__ unsigned g_rowsU[(size_t)PLANES*NPOS*3]; // row0 bytes, 4/u32, pad=200
__device__ unsigned g_colsU[(size_t)PLANES*NPOS*3]; // col0 bytes

// ---------------- f32x2 helpers ----------------------------------------------
__device__ __forceinline__ unsigned long long pk2(float lo, float hi) {
    unsigned long long r;
    asm("mov.b64 %0, {%1, %2};" : "=l"(r) : "f"(lo), "f"(hi));
    return r;
}
__device__ __forceinline__ void fma2(unsigned long long& acc, unsigned long long a,
                                     unsigned long long b) {
    asm("fma.rn.f32x2 %0, %1, %2, %3;" : "=l"(acc) : "l"(a), "l"(b), "l"(acc));
}
__device__ __forceinline__ void upk2(unsigned long long v, float& lo, float& hi) {
    asm("mov.b64 {%0, %1}, %2;" : "=f"(lo), "=f"(hi) : "l"(v));
}

// ---------------- K-1: dummy (shifts ncu capture slot onto a real kernel) ----
__global__ void k_dummy() {}

// ---------------- K0: fuse the two projections (block per output row) --------
__global__ __launch_bounds__(64) void k_precompute(const float* __restrict__ Wp,
                                                   const float* __restrict__ bp,
                                                   const float* __restrict__ pe,
                                                   const float* __restrict__ Wb,
                                                   const float* __restrict__ bb) {
    const int row = blockIdx.x;   // 0..48 -> M rows, 49..58 -> v rows
    const int t = threadIdx.x;
    __shared__ float sRow[128];
    if (row < 49) {
        for (int e = t; e < 128; e += 64) sRow[e] = Wp[row*128 + e];
    } else {
        const int n = row - 49;
        for (int e = t; e < 128; e += 64) sRow[e] = bp[e] + pe[n*128 + e];
    }
    __syncthreads();
    for (int q = t; q < 49; q += 64) {
        float acc = (row < 49) ? 0.f : bb[q];
        #pragma unroll 8
        for (int e = 0; e < 128; e++) acc += sRow[e] * Wb[e*49 + q];
        if (row < 49) g_M[row*49 + q] = acc;
        else          g_v[(row-49)*49 + q] = acc;
    }
}

// ---------------- K1: warp-per-(pos,plane) stage1 ----------------------------
__global__ __launch_bounds__(256) void k_stage1(const float* __restrict__ images) {
    const int warp = threadIdx.x >> 5;
    const int lane = threadIdx.x & 31;
    const int pos   = blockIdx.x * 8 + warp;
    const int plane = blockIdx.y;

    const int ixp = pos / GRID1D;      // x outer
    const int iyp = pos % GRID1D;      // y inner
    const int x = ixp * 4, y = iyp * 4;
    const int xb0 = max(x - 7, 0), yb0 = max(y - 7, 0);
    const int winW = min(x + 13, WW) - xb0;
    const int winH = min(y + 13, HH) - yb0;
    const int rx = x - xb0, ry = y - yb0;   // ref offset inside window

    __shared__ float sWinAll[8][400];
    __shared__ __align__(16) float sPTAll[8][588];   // 49 x 12 padded
    __shared__ int   sIdsAll[8][10];
    __shared__ int   sOffAll[8][10];
    float* sWin = sWinAll[warp];
    float* sPT  = sPTAll[warp];
    int*   sIds = sIdsAll[warp];
    int*   sOff = sOffAll[warp];

    const float* img = images + (size_t)plane * (HH*WW);
    #pragma unroll
    for (int o = lane; o < 400; o += 32)
        sWin[o] = img[(yb0 + o/20)*WW + xb0 + o%20];
    __syncwarp();

    // sliding-window conv: lane -> (row i, half), 7 contiguous outputs each
    const int i  = min(lane >> 1, 13);     // 0..13
    const int hf = lane & 1;               // 0/1
    const int j0 = hf * 7;                 // 0 or 7
    float acc[7];
    #pragma unroll
    for (int m = 0; m < 7; m++) acc[m] = 0.f;
    #pragma unroll
    for (int dy = 0; dy < 7; dy++) {
        float w[13];
        const int rb = (i + dy)*20 + j0;
        #pragma unroll
        for (int c = 0; c < 13; c++) w[c] = sWin[rb + c];
        #pragma unroll
        for (int dx = 0; dx < 7; dx++) {
            const float rv = sWin[(ry + dy)*20 + rx + dx];
            #pragma unroll
            for (int m = 0; m < 7; m++)
                acc[m] += w[m + dx] * rv;
        }
    }

    // unique ordering keys; o = i*14 + j0 + m
    const float NEG_INF = -__int_as_float(0x7f800000);
    unsigned long long keys[7];
    #pragma unroll
    for (int m = 0; m < 7; m++) {
        const int j = j0 + m;
        const int o = i*14 + j;
        const float sim = (i <= winH - 7 && j <= winW - 7) ? acc[m] : NEG_INF;
        const unsigned b = __float_as_uint(sim);
        const unsigned ord = (b & 0x80000000u) ? ~b : (b | 0x80000000u);
        keys[m] = (lane < 28) ? (((unsigned long long)ord << 32) | (unsigned)(65535 - o))
                              : 0ull;
    }

    // exact top-10: 10 rounds of warp max-extraction (keys unique)
    int ids[10];
    #pragma unroll
    for (int r = 0; r < 10; r++) {
        unsigned long long best = keys[0];
        #pragma unroll
        for (int m = 1; m < 7; m++) if (keys[m] > best) best = keys[m];
        #pragma unroll
        for (int s = 16; s; s >>= 1) {
            const unsigned long long o2 = __shfl_xor_sync(0xffffffffu, best, s);
            if (o2 > best) best = o2;
        }
        const int id = 65535 - (int)(best & 0xffffu);
        ids[r] = id;
        const int bi = id / 14, bj = id % 14;
        const int ownLane = (bi << 1) | (bj >= 7);
        if (lane == ownLane) {
            const int mw = bj - ((bj >= 7) ? 7 : 0);
            #pragma unroll
            for (int mm = 0; mm < 7; mm++) if (mm == mw) keys[mm] = 0ull;
        }
    }
    if (lane == 0) {
        #pragma unroll
        for (int n = 0; n < 10; n++) {
            sIds[n] = ids[n];
            sOff[n] = (ids[n] / 14) * 20 + (ids[n] % 14);
        }
    }
    __syncwarp();

    // extract transposed patches: sPT[k*12+n] = win[oy+k%7][ox+k/7]
    for (int e = lane; e < 490; e += 32) {
        const int k = e / 10, n = e - k*10;
        sPT[k*12 + n] = sWin[sOff[n] + (k % 7)*20 + (k / 7)];
    }
    // coord words (source bug preserved: row0 = col-offset + yb0, col0 = row-offset + xb0)
    if (lane < 6) {
        const int w = lane;
        const int widx = (w < 3) ? w : w - 3;
        unsigned v = 0;
        #pragma unroll
        for (int p = 0; p < 4; p++) {
            const int nn = widx*4 + p;
            unsigned byte = 200;
            if (nn < 10) {
                const int id = sIds[nn];
                byte = (w < 3) ? (unsigned)(id % 14 + yb0)    // row0
                               : (unsigned)(id / 14 + xb0);   // col0
            }
            v |= byte << (p * 8);
        }
        unsigned* dst = (w < 3) ? g_rowsU : g_colsU;
        dst[((size_t)plane*NPOS + pos)*3 + widx] = v;
    }
    __syncwarp();

    // den[n][q] = sum_k patchT[k][n] * M[k][q] + v[n][q]
    // f32x2 packed FMA: pairs over n; q1 = lane, q2 = lane + 32 (lane < 17)
    {
        const int q1 = lane;
        const int q2 = lane + 32;
        const bool has2 = (q2 < 49);
        unsigned long long accA[5], accB[5];
        #pragma unroll
        for (int j = 0; j < 5; j++) { accA[j] = 0ull; accB[j] = 0ull; }
        const float4* P4 = (const float4*)sPT;
        #pragma unroll 7
        for (int k = 0; k < 49; k++) {
            const float m1 = __ldg(&g_M[k*49 + q1]);
            const float m2 = has2 ? __ldg(&g_M[k*49 + q2]) : 0.f;
            const unsigned long long m1p = pk2(m1, m1);
            const unsigned long long m2p = pk2(m2, m2);
            const float4 pa = P4[k*3 + 0];
            const float4 pb = P4[k*3 + 1];
            const float4 pc = P4[k*3 + 2];
            const unsigned long long p01 = pk2(pa.x, pa.y);
            const unsigned long long p23 = pk2(pa.z, pa.w);
            const unsigned long long p45 = pk2(pb.x, pb.y);
            const unsigned long long p67 = pk2(pb.z, pb.w);
            const unsigned long long p89 = pk2(pc.x, pc.y);
            fma2(accA[0], m1p, p01); fma2(accA[1], m1p, p23);
            fma2(accA[2], m1p, p45); fma2(accA[3], m1p, p67);
            fma2(accA[4], m1p, p89);
            fma2(accB[0], m2p, p01); fma2(accB[1], m2p, p23);
            fma2(accB[2], m2p, p45); fma2(accB[3], m2p, p67);
            fma2(accB[4], m2p, p89);
        }
        float a[10], b2[10];
        #pragma unroll
        for (int j = 0; j < 5; j++) {
            upk2(accA[j], a[2*j], a[2*j+1]);
            upk2(accB[j], b2[2*j], b2[2*j+1]);
        }
        float* denOut = g_den + ((size_t)plane * STEPS + (size_t)pos * NP) * 49;
        #pragma unroll
        for (int n = 0; n < 10; n++) {
            denOut[n*49 + q1] = a[n] + __ldg(&g_v[n*49 + q1]);
            if (has2) denOut[n*49 + q2] = b2[n] + __ldg(&g_v[n*49 + q2]);
        }
    }
}

// ---------------- K2: role-split mask-table fold ------------------------------
__device__ __forceinline__ int flo(int c) { return (c <= 19) ? 0 : ((c - 9) >> 2); }
__device__ __forceinline__ int fhi(int c) { return min(GRID1D - 1, (c + 7) >> 2); }
__device__ __forceinline__ unsigned pack4(unsigned hm) {
    return ((hm & 0x01010101u) * 0x01020408u) >> 24;   // byte flags -> 4 bits
}
__device__ __forceinline__ unsigned mask10(unsigned vrep, const unsigned* p) {
    const unsigned seven = 0x07070707u;
    unsigned m0 = __vcmpltu4(__vsub4(vrep, p[0]), seven);
    unsigned m1 = __vcmpltu4(__vsub4(vrep, p[1]), seven);
    unsigned m2 = __vcmpltu4(__vsub4(vrep, p[2]), seven);
    return pack4(m0) | (pack4(m1) << 4) | (pack4(m2) << 8);
}

__global__ __launch_bounds__(256) void k_fold(const float* __restrict__ images,
                                              float* __restrict__ out) {
    const int plane = blockIdx.y;
    const int tile  = blockIdx.x;               // 0..99
    const int TR = (tile / 10) * 16, TC = (tile % 10) * 16;
    const int t = threadIdx.x;
    const int r  = TR + (t >> 4);
    const int cc = TC + (t & 15);

    const int Rlo = flo(TR), Rhi = fhi(TR + 15);
    const int Clo = flo(TC), Chi = fhi(TC + 15);
    const int rW = Rhi - Rlo + 1;               // <= 10
    const int cW = Chi - Clo + 1;               // <= 10
    const int nCell = rW * cW;                  // im and cnt rects have same count

    __shared__ unsigned sImR[100*3], sImC[100*3];   // im cells: ix-Clo major, iy-Rlo minor
    __shared__ unsigned sCnR[100*3], sCnC[100*3];   // cnt cells: ix-Rlo major, iy-Clo minor
    __shared__ unsigned short tRvR[100*16], tCvC[100*16]; // im masks
    __shared__ unsigned short tRvC[100*16], tCvR[100*16]; // cnt masks
    __shared__ float sRecip[96];

    for (int s = t; s < nCell*3; s += 256) {
        const int slot = s / 3, w = s - slot*3;
        const int ixo = slot / rW, iyo = slot - ixo*rW;
        const size_t g = ((size_t)plane*NPOS + (Clo + ixo)*GRID1D + (Rlo + iyo))*3 + w;
        sImR[s] = g_rowsU[g]; sImC[s] = g_colsU[g];
        const int ixo2 = slot / cW, iyo2 = slot - ixo2*cW;
        const size_t g2 = ((size_t)plane*NPOS + (Rlo + ixo2)*GRID1D + (Clo + iyo2))*3 + w;
        sCnR[s] = g_rowsU[g2]; sCnC[s] = g_colsU[g2];
    }
    if (t < 96) sRecip[t] = t ? (1.0f / (float)t) : 0.f;
    __syncthreads();

    for (int e = t; e < nCell*16; e += 256) {
        const int slot = e >> 4, i = e & 15;
        const unsigned rv = (unsigned)(TR + i) * 0x01010101u;
        const unsigned cv = (unsigned)(TC + i) * 0x01010101u;
        tRvR[e] = (unsigned short)mask10(rv, &sImR[slot*3]);
        tCvC[e] = (unsigned short)mask10(cv, &sImC[slot*3]);
        tRvC[e] = (unsigned short)mask10(rv, &sCnC[slot*3]);
        tCvR[e] = (unsigned short)mask10(cv, &sCnR[slot*3]);
    }
    __syncthreads();

    float val = images[(size_t)plane * (HH*WW) + r * WW + cc];

    // im role: ix in f(cc), iy in f(r).  cnt role: ix in f(r), iy in f(cc).
    const int imXLo = flo(cc), imXHi = fhi(cc);
    const int cnXLo = flo(r),  cnXHi = fhi(r);
    const int rp = r - TR, cp = cc - TC;
    const float* den = g_den + (size_t)plane * STEPS * 49;

    if (imXLo <= imXHi && cnXLo <= cnXHi) {
        const bool cntFirst = (cnXHi < imXLo);
        const bool imFirst  = (imXHi < cnXLo);
        if (cntFirst | imFirst) {
            // ---- disjoint ranges: constant count for every im hit ----
            int tot = 0;
            if (cntFirst) {
                for (int ix = cnXLo; ix <= cnXHi; ix++) {
                    const int base = (ix - Rlo) * cW;
                    #pragma unroll 3
                    for (int iy = imXLo; iy <= imXHi; iy++) {
                        const int slot = base + iy - Clo;
                        tot += __popc((unsigned)tRvC[slot*16 + rp] &
                                      (unsigned)tCvR[slot*16 + cp]);
                    }
                }
            }
            const int c = 1 + tot;
            const float G = sRecip[c + 1];
            const float F = (float)c * G;
            for (int ix = imXLo; ix <= imXHi; ix++) {
                const int imRow = (ix - Clo) * rW;
                #pragma unroll 3
                for (int iy = cnXLo; iy <= cnXHi; iy++) {
                    const int slot = imRow + iy - Rlo;
                    unsigned m = (unsigned)tRvR[slot*16 + rp] &
                                 (unsigned)tCvC[slot*16 + cp];
                    if (m) {
                        const int stepBase = (ix*GRID1D + iy) * NP;
                        do {
                            const int n = __ffs(m) - 1; m &= m - 1;
                            const int row0 = (sImR[slot*3 + (n >> 2)] >> ((n & 3)*8)) & 0xff;
                            const int col0 = (sImC[slot*3 + (n >> 2)] >> ((n & 3)*8)) & 0xff;
                            const float d = __ldg(den + (size_t)(stepBase + n)*49
                                                      + (r - row0)*7 + (cc - col0));
                            val = val * F + d * G;
                        } while (m);
                    }
                }
            }
        } else {
            // ---- overlapping ranges: merged step-ordered scan ----
            int pcnt = 1;
            const int xF = min(imXLo, cnXLo), xL = max(imXHi, cnXHi);
            for (int ix = xF; ix <= xL; ix++) {
                const bool okIm = (ix >= imXLo) & (ix <= imXHi);
                const bool okCn = (ix >= cnXLo) & (ix <= cnXHi);
                const int imRow = (ix - Clo) * rW;
                const int cnRow = (ix - Rlo) * cW;
                for (int iy = xF; iy <= xL; iy++) {
                    const bool hIm = okIm & (iy >= cnXLo) & (iy <= cnXHi);
                    const bool hCn = okCn & (iy >= imXLo) & (iy <= imXHi);
                    if (!hIm && !hCn) continue;
                    unsigned maskIm = 0, maskCn = 0;
                    int imSlot = 0;
                    if (hIm) {
                        imSlot = imRow + iy - Rlo;
                        maskIm = (unsigned)tRvR[imSlot*16 + rp] &
                                 (unsigned)tCvC[imSlot*16 + cp];
                    }
                    if (hCn) {
                        const int cnSlot = cnRow + iy - Clo;
                        maskCn = (unsigned)tRvC[cnSlot*16 + rp] &
                                 (unsigned)tCvR[cnSlot*16 + cp];
                    }
                    if (maskIm) {
                        const int stepBase = (ix*GRID1D + iy) * NP;
                        unsigned m = maskIm;
                        do {
                            const int n = __ffs(m) - 1; m &= m - 1;
                            const int cntNow = pcnt + __popc(maskCn & ((1u << n) - 1u));
                            const int row0 = (sImR[imSlot*3 + (n >> 2)] >> ((n & 3)*8)) & 0xff;
                            const int col0 = (sImC[imSlot*3 + (n >> 2)] >> ((n & 3)*8)) & 0xff;
                            const float d = __ldg(den + (size_t)(stepBase + n)*49
                                                      + (r - row0)*7 + (cc - col0));
                            val = (val * (float)cntNow + d) * sRecip[cntNow + 1];
                        } while (m);
                    }
                    pcnt += __popc(maskCn);
                }
            }
        }
    }
    out[(size_t)plane * (HH*WW) + r * WW + cc] = val;
}

// ---------------- launch ------------------------------------------------------
extern "C" void kernel_launch(void* const* d_in, const int* in_sizes, int n_in,
                              void* d_out, int out_size) {
    const float* images = (const float*)d_in[0];
    const float* Wp     = (const float*)d_in[1];
    const float* bp     = (const float*)d_in[2];
    const float* pe     = (const float*)d_in[3];
    const float* Wb     = (const float*)d_in[4];
    const float* bb     = (const float*)d_in[5];
    float* out = (float*)d_out;
    (void)in_sizes; (void)n_in; (void)out_size;

    k_dummy<<<1, 32>>>();

    k_precompute<<<59, 64>>>(Wp, bp, pe, Wb, bb);

    dim3 g1(162, PLANES);
    k_stage1<<<g1, 256>>>(images);

    dim3 g2(100, PLANES);
    k_fold<<<g2, 256>>>(images, out);
}

// round 14
// speedup vs baseline: 3.0564x; 1.0353x over previous
#include <cuda_runtime.h>

#define NPOS 1296
#define GRID1D 36
#define PP 7
#define NP 10
#define WINS 20
#define LL 14
#define HH 160
#define WW 160
#define PLANES 32
#define STEPS (NPOS*NP)   // 12960

// ---------------- scratch (static device globals; no runtime allocation) ----
__device__ float    g_M[49*49];              // Wp @ Wb
__device__ float    g_v[NP*49];              // (bp + pos_emb[n]) @ Wb + bb
__device__ float    g_den[(size_t)PLANES*STEPS*49]; // ~81 MB
__device__ unsigned g_rowsU[(size_t)PLANES*NPOS*3]; // row0 bytes, 4/u32, pad=200
__device__ unsigned g_colsU[(size_t)PLANES*NPOS*3]; // col0 bytes

// ---------------- f32x2 helpers ----------------------------------------------
__device__ __forceinline__ unsigned long long pk2(float lo, float hi) {
    unsigned long long r;
    asm("mov.b64 %0, {%1, %2};" : "=l"(r) : "f"(lo), "f"(hi));
    return r;
}
__device__ __forceinline__ void fma2(unsigned long long& acc, unsigned long long a,
                                     unsigned long long b) {
    asm("fma.rn.f32x2 %0, %1, %2, %3;" : "=l"(acc) : "l"(a), "l"(b), "l"(acc));
}
__device__ __forceinline__ void upk2(unsigned long long v, float& lo, float& hi) {
    asm("mov.b64 {%0, %1}, %2;" : "=f"(lo), "=f"(hi) : "l"(v));
}

// ---------------- K-1: dummy (keeps ncu capture slot on k_fold) --------------
__global__ void k_dummy() {}

// ---------------- K0: fuse the two projections (block per output row) --------
__global__ __launch_bounds__(64) void k_precompute(const float* __restrict__ Wp,
                                                   const float* __restrict__ bp,
                                                   const float* __restrict__ pe,
                                                   const float* __restrict__ Wb,
                                                   const float* __restrict__ bb) {
    const int row = blockIdx.x;   // 0..48 -> M rows, 49..58 -> v rows
    const int t = threadIdx.x;
    __shared__ float sRow[128];
    if (row < 49) {
        for (int e = t; e < 128; e += 64) sRow[e] = Wp[row*128 + e];
    } else {
        const int n = row - 49;
        for (int e = t; e < 128; e += 64) sRow[e] = bp[e] + pe[n*128 + e];
    }
    __syncthreads();
    for (int q = t; q < 49; q += 64) {
        float acc = (row < 49) ? 0.f : bb[q];
        #pragma unroll 8
        for (int e = 0; e < 128; e++) acc += sRow[e] * Wb[e*49 + q];
        if (row < 49) g_M[row*49 + q] = acc;
        else          g_v[(row-49)*49 + q] = acc;
    }
}

// ---------------- K1: warp-per-(pos,plane) stage1 ----------------------------
__global__ __launch_bounds__(256) void k_stage1(const float* __restrict__ images) {
    const int warp = threadIdx.x >> 5;
    const int lane = threadIdx.x & 31;
    const int pos   = blockIdx.x * 8 + warp;
    const int plane = blockIdx.y;

    const int ixp = pos / GRID1D;      // x outer
    const int iyp = pos % GRID1D;      // y inner
    const int x = ixp * 4, y = iyp * 4;
    const int xb0 = max(x - 7, 0), yb0 = max(y - 7, 0);
    const int winW = min(x + 13, WW) - xb0;
    const int winH = min(y + 13, HH) - yb0;
    const int rx = x - xb0, ry = y - yb0;   // ref offset inside window

    __shared__ float sWinAll[8][400];
    __shared__ __align__(16) float sPTAll[8][588];   // 49 x 12 padded
    __shared__ int   sIdsAll[8][10];
    __shared__ int   sOffAll[8][10];
    float* sWin = sWinAll[warp];
    float* sPT  = sPTAll[warp];
    int*   sIds = sIdsAll[warp];
    int*   sOff = sOffAll[warp];

    const float* img = images + (size_t)plane * (HH*WW);
    #pragma unroll
    for (int o = lane; o < 400; o += 32)
        sWin[o] = img[(yb0 + o/20)*WW + xb0 + o%20];
    __syncwarp();

    // sliding-window conv: lane -> (row i, half), 7 contiguous outputs each
    const int i  = min(lane >> 1, 13);     // 0..13
    const int hf = lane & 1;               // 0/1
    const int j0 = hf * 7;                 // 0 or 7
    float acc[7];
    #pragma unroll
    for (int m = 0; m < 7; m++) acc[m] = 0.f;
    #pragma unroll
    for (int dy = 0; dy < 7; dy++) {
        float w[13];
        const int rb = (i + dy)*20 + j0;
        #pragma unroll
        for (int c = 0; c < 13; c++) w[c] = sWin[rb + c];
        #pragma unroll
        for (int dx = 0; dx < 7; dx++) {
            const float rv = sWin[(ry + dy)*20 + rx + dx];
            #pragma unroll
            for (int m = 0; m < 7; m++)
                acc[m] += w[m + dx] * rv;
        }
    }

    // unique ordering keys; o = i*14 + j0 + m
    const float NEG_INF = -__int_as_float(0x7f800000);
    unsigned long long keys[7];
    #pragma unroll
    for (int m = 0; m < 7; m++) {
        const int j = j0 + m;
        const int o = i*14 + j;
        const float sim = (i <= winH - 7 && j <= winW - 7) ? acc[m] : NEG_INF;
        const unsigned b = __float_as_uint(sim);
        const unsigned ord = (b & 0x80000000u) ? ~b : (b | 0x80000000u);
        keys[m] = (lane < 28) ? (((unsigned long long)ord << 32) | (unsigned)(65535 - o))
                              : 0ull;
    }

    // exact top-10: 10 rounds of warp max-extraction (keys unique)
    int ids[10];
    #pragma unroll
    for (int r = 0; r < 10; r++) {
        unsigned long long best = keys[0];
        #pragma unroll
        for (int m = 1; m < 7; m++) if (keys[m] > best) best = keys[m];
        #pragma unroll
        for (int s = 16; s; s >>= 1) {
            const unsigned long long o2 = __shfl_xor_sync(0xffffffffu, best, s);
            if (o2 > best) best = o2;
        }
        const int id = 65535 - (int)(best & 0xffffu);
        ids[r] = id;
        const int bi = id / 14, bj = id % 14;
        const int ownLane = (bi << 1) | (bj >= 7);
        if (lane == ownLane) {
            const int mw = bj - ((bj >= 7) ? 7 : 0);
            #pragma unroll
            for (int mm = 0; mm < 7; mm++) if (mm == mw) keys[mm] = 0ull;
        }
    }
    if (lane == 0) {
        #pragma unroll
        for (int n = 0; n < 10; n++) {
            sIds[n] = ids[n];
            sOff[n] = (ids[n] / 14) * 20 + (ids[n] % 14);
        }
    }
    __syncwarp();

    // extract transposed patches: sPT[k*12+n] = win[oy+k%7][ox+k/7]
    for (int e = lane; e < 490; e += 32) {
        const int k = e / 10, n = e - k*10;
        sPT[k*12 + n] = sWin[sOff[n] + (k % 7)*20 + (k / 7)];
    }
    // coord words (source bug preserved: row0 = col-offset + yb0, col0 = row-offset + xb0)
    if (lane < 6) {
        const int w = lane;
        const int widx = (w < 3) ? w : w - 3;
        unsigned v = 0;
        #pragma unroll
        for (int p = 0; p < 4; p++) {
            const int nn = widx*4 + p;
            unsigned byte = 200;
            if (nn < 10) {
                const int id = sIds[nn];
                byte = (w < 3) ? (unsigned)(id % 14 + yb0)    // row0
                               : (unsigned)(id / 14 + xb0);   // col0
            }
            v |= byte << (p * 8);
        }
        unsigned* dst = (w < 3) ? g_rowsU : g_colsU;
        dst[((size_t)plane*NPOS + pos)*3 + widx] = v;
    }
    __syncwarp();

    // den[n][q] = sum_k patchT[k][n] * M[k][q] + v[n][q]
    // f32x2 packed FMA; patch pairs read directly as 64-bit lanes of LDS.128
    {
        const int q1 = lane;
        const int q2 = lane + 32;
        const bool has2 = (q2 < 49);
        unsigned long long accA[5], accB[5];
        #pragma unroll
        for (int j = 0; j < 5; j++) { accA[j] = 0ull; accB[j] = 0ull; }
        const ulonglong2* U2 = (const ulonglong2*)sPT;
        #pragma unroll 7
        for (int k = 0; k < 49; k++) {
            const float m1 = __ldg(&g_M[k*49 + q1]);
            const float m2 = has2 ? __ldg(&g_M[k*49 + q2]) : 0.f;
            const unsigned long long m1p = pk2(m1, m1);
            const unsigned long long m2p = pk2(m2, m2);
            const ulonglong2 A = U2[k*3 + 0];
            const ulonglong2 B = U2[k*3 + 1];
            const ulonglong2 C = U2[k*3 + 2];
            fma2(accA[0], m1p, A.x); fma2(accA[1], m1p, A.y);
            fma2(accA[2], m1p, B.x); fma2(accA[3], m1p, B.y);
            fma2(accA[4], m1p, C.x);
            fma2(accB[0], m2p, A.x); fma2(accB[1], m2p, A.y);
            fma2(accB[2], m2p, B.x); fma2(accB[3], m2p, B.y);
            fma2(accB[4], m2p, C.x);
        }
        float a[10], b2[10];
        #pragma unroll
        for (int j = 0; j < 5; j++) {
            upk2(accA[j], a[2*j], a[2*j+1]);
            upk2(accB[j], b2[2*j], b2[2*j+1]);
        }
        float* denOut = g_den + ((size_t)plane * STEPS + (size_t)pos * NP) * 49;
        #pragma unroll
        for (int n = 0; n < 10; n++) {
            denOut[n*49 + q1] = a[n] + __ldg(&g_v[n*49 + q1]);
            if (has2) denOut[n*49 + q2] = b2[n] + __ldg(&g_v[n*49 + q2]);
        }
    }
}

// ---------------- K2: role-split mask-table fold + precomputed den bases -----
__device__ __forceinline__ int flo(int c) { return (c <= 19) ? 0 : ((c - 9) >> 2); }
__device__ __forceinline__ int fhi(int c) { return min(GRID1D - 1, (c + 7) >> 2); }
__device__ __forceinline__ unsigned pack4(unsigned hm) {
    return ((hm & 0x01010101u) * 0x01020408u) >> 24;   // byte flags -> 4 bits
}
__device__ __forceinline__ unsigned mask10(unsigned vrep, const unsigned* p) {
    const unsigned seven = 0x07070707u;
    unsigned m0 = __vcmpltu4(__vsub4(vrep, p[0]), seven);
    unsigned m1 = __vcmpltu4(__vsub4(vrep, p[1]), seven);
    unsigned m2 = __vcmpltu4(__vsub4(vrep, p[2]), seven);
    return pack4(m0) | (pack4(m1) << 4) | (pack4(m2) << 8);
}

__global__ __launch_bounds__(256) void k_fold(const float* __restrict__ images,
                                              float* __restrict__ out) {
    const int plane = blockIdx.y;
    const int tile  = blockIdx.x;               // 0..99
    const int TR = (tile / 10) * 16, TC = (tile % 10) * 16;
    const int t = threadIdx.x;
    const int r  = TR + (t >> 4);
    const int cc = TC + (t & 15);

    const int Rlo = flo(TR), Rhi = fhi(TR + 15);
    const int Clo = flo(TC), Chi = fhi(TC + 15);
    const int rW = Rhi - Rlo + 1;               // <= 10
    const int cW = Chi - Clo + 1;               // <= 10
    const int nCell = rW * cW;                  // im and cnt rects have same count

    __shared__ unsigned sImR[100*3], sImC[100*3];   // im cells: ix-Clo major, iy-Rlo minor
    __shared__ unsigned sCnR[100*3], sCnC[100*3];   // cnt cells: ix-Rlo major, iy-Clo minor
    __shared__ unsigned short tRvR[100*16], tCvC[100*16]; // im masks
    __shared__ unsigned short tRvC[100*16], tCvR[100*16]; // cnt masks
    __shared__ int sBaseIm[100*10];   // den index base: step*49 - row0*7 - col0
    __shared__ float sRecip[96];

    for (int s = t; s < nCell*3; s += 256) {
        const int slot = s / 3, w = s - slot*3;
        const int ixo = slot / rW, iyo = slot - ixo*rW;
        const size_t g = ((size_t)plane*NPOS + (Clo + ixo)*GRID1D + (Rlo + iyo))*3 + w;
        sImR[s] = g_rowsU[g]; sImC[s] = g_colsU[g];
        const int ixo2 = slot / cW, iyo2 = slot - ixo2*cW;
        const size_t g2 = ((size_t)plane*NPOS + (Rlo + ixo2)*GRID1D + (Clo + iyo2))*3 + w;
        sCnR[s] = g_rowsU[g2]; sCnC[s] = g_colsU[g2];
    }
    if (t < 96) sRecip[t] = t ? (1.0f / (float)t) : 0.f;
    __syncthreads();

    for (int e = t; e < nCell*16; e += 256) {
        const int slot = e >> 4, i = e & 15;
        const unsigned rv = (unsigned)(TR + i) * 0x01010101u;
        const unsigned cv = (unsigned)(TC + i) * 0x01010101u;
        tRvR[e] = (unsigned short)mask10(rv, &sImR[slot*3]);
        tCvC[e] = (unsigned short)mask10(cv, &sImC[slot*3]);
        tRvC[e] = (unsigned short)mask10(rv, &sCnC[slot*3]);
        tCvR[e] = (unsigned short)mask10(cv, &sCnR[slot*3]);
    }
    // den base per (im cell, candidate): step*49 - row0*7 - col0
    for (int e = t; e < nCell*10; e += 256) {
        const int slot = e / 10, n = e - slot*10;
        const int ixo = slot / rW, iyo = slot - ixo*rW;
        const int step = (((Clo + ixo)*GRID1D) + (Rlo + iyo))*NP + n;
        const int row0 = (sImR[slot*3 + (n >> 2)] >> ((n & 3)*8)) & 0xff;
        const int col0 = (sImC[slot*3 + (n >> 2)] >> ((n & 3)*8)) & 0xff;
        sBaseIm[e] = step*49 - row0*7 - col0;
    }
    __syncthreads();

    float val = images[(size_t)plane * (HH*WW) + r * WW + cc];

    // im role: ix in f(cc), iy in f(r).  cnt role: ix in f(r), iy in f(cc).
    const int imXLo = flo(cc), imXHi = fhi(cc);
    const int cnXLo = flo(r),  cnXHi = fhi(r);
    const int rp = r - TR, cp = cc - TC;
    const int pixOff = r*7 + cc;
    const float* den = g_den + (size_t)plane * STEPS * 49;

    if (imXLo <= imXHi && cnXLo <= cnXHi) {
        const bool cntFirst = (cnXHi < imXLo);
        const bool imFirst  = (imXHi < cnXLo);
        if (cntFirst | imFirst) {
            // ---- disjoint ranges: constant count for every im hit ----
            int tot = 0;
            if (cntFirst) {
                for (int ix = cnXLo; ix <= cnXHi; ix++) {
                    const int base = (ix - Rlo) * cW;
                    #pragma unroll 3
                    for (int iy = imXLo; iy <= imXHi; iy++) {
                        const int slot = base + iy - Clo;
                        tot += __popc((unsigned)tRvC[slot*16 + rp] &
                                      (unsigned)tCvR[slot*16 + cp]);
                    }
                }
            }
            const int c = 1 + tot;
            const float G = sRecip[c + 1];
            const float F = (float)c * G;
            for (int ix = imXLo; ix <= imXHi; ix++) {
                const int imRow = (ix - Clo) * rW;
                #pragma unroll 3
                for (int iy = cnXLo; iy <= cnXHi; iy++) {
                    const int slot = imRow + iy - Rlo;
                    unsigned m = (unsigned)tRvR[slot*16 + rp] &
                                 (unsigned)tCvC[slot*16 + cp];
                    while (m) {
                        const int n = __ffs(m) - 1; m &= m - 1;
                        const float d = __ldg(den + sBaseIm[slot*10 + n] + pixOff);
                        val = val * F + d * G;
                    }
                }
            }
        } else {
            // ---- overlapping ranges: merged step-ordered scan ----
            int pcnt = 1;
            const int xF = min(imXLo, cnXLo), xL = max(imXHi, cnXHi);
            for (int ix = xF; ix <= xL; ix++) {
                const bool okIm = (ix >= imXLo) & (ix <= imXHi);
                const bool okCn = (ix >= cnXLo) & (ix <= cnXHi);
                const int imRow = (ix - Clo) * rW;
                const int cnRow = (ix - Rlo) * cW;
                for (int iy = xF; iy <= xL; iy++) {
                    const bool hIm = okIm & (iy >= cnXLo) & (iy <= cnXHi);
                    const bool hCn = okCn & (iy >= imXLo) & (iy <= imXHi);
                    if (!hIm && !hCn) continue;
                    unsigned maskIm = 0, maskCn = 0;
                    int imSlot = 0;
                    if (hIm) {
                        imSlot = imRow + iy - Rlo;
                        maskIm = (unsigned)tRvR[imSlot*16 + rp] &
                                 (unsigned)tCvC[imSlot*16 + cp];
                    }
                    if (hCn) {
                        const int cnSlot = cnRow + iy - Clo;
                        maskCn = (unsigned)tRvC[cnSlot*16 + rp] &
                                 (unsigned)tCvR[cnSlot*16 + cp];
                    }
                    while (maskIm) {
                        const int n = __ffs(maskIm) - 1; maskIm &= maskIm - 1;
                        const int cntNow = pcnt + __popc(maskCn & ((1u << n) - 1u));
                        const float d = __ldg(den + sBaseIm[imSlot*10 + n] + pixOff);
                        val = (val * (float)cntNow + d) * sRecip[cntNow + 1];
                    }
                    pcnt += __popc(maskCn);
                }
            }
        }
    }
    out[(size_t)plane * (HH*WW) + r * WW + cc] = val;
}

// ---------------- launch ------------------------------------------------------
extern "C" void kernel_launch(void* const* d_in, const int* in_sizes, int n_in,
                              void* d_out, int out_size) {
    const float* images = (const float*)d_in[0];
    const float* Wp     = (const float*)d_in[1];
    const float* bp     = (const float*)d_in[2];
    const float* pe     = (const float*)d_in[3];
    const float* Wb     = (const float*)d_in[4];
    const float* bb     = (const float*)d_in[5];
    float* out = (float*)d_out;
    (void)in_sizes; (void)n_in; (void)out_size;

    k_dummy<<<1, 32>>>();

    k_precompute<<<59, 64>>>(Wp, bp, pe, Wb, bb);

    dim3 g1(162, PLANES);
    k_stage1<<<g1, 256>>>(images);

    dim3 g2(100, PLANES);
    k_fold<<<g2, 256>>>(images, out);
}